// round 8
// baseline (speedup 1.0000x reference)
#include <cuda_runtime.h>
#include <cstdint>

#define BB 64
#define TT 256
#define UU 512
#define GG 2048
#define BT (BB*TT)

#define NBLK 128
#define HS2 516                                    // h_s row stride (float4-aligned, conflict-free)
#define SCAN_SMEM ((256*64 + BB*HS2) * 4)          // w_s 64KB + h_s 132KB = 197632 B

// ---------------- static scratch ----------------
__device__ __align__(128) float g_x0 [BT * 512];
__device__ __align__(128) float g_y0 [BT * 1024];
__device__ __align__(128) float g_xzf[BT * GG];
__device__ __align__(128) float g_xzb[BT * GG];
__device__ __align__(128) float g_h  [2 * 2 * BB * UU];   // [buf][dir][row][unit]
__device__ unsigned g_bar_count = 0;
__device__ unsigned g_bar_gen   = 0;

// ---------------- packed fp32 helpers ----------------
__device__ __forceinline__ void fma2(unsigned long long& d, unsigned long long a,
                                     unsigned long long b) {
    asm("fma.rn.f32x2 %0, %1, %2, %0;" : "+l"(d) : "l"(a), "l"(b));
}
__device__ __forceinline__ float2 up2(unsigned long long u) {
    float2 f; asm("mov.b64 {%0,%1}, %2;" : "=f"(f.x), "=f"(f.y) : "l"(u)); return f;
}
__device__ __forceinline__ float sigf(float x) { return 1.0f / (1.0f + expf(-x)); }

// R2-proven central grid barrier (fence + single atomic + spin)
__device__ __forceinline__ void grid_barrier() {
    __threadfence();
    __syncthreads();
    if (threadIdx.x == 0) {
        unsigned gen = *(volatile unsigned*)&g_bar_gen;
        if (atomicAdd(&g_bar_count, 1u) == NBLK - 1) {
            g_bar_count = 0;
            __threadfence();
            *(volatile unsigned*)&g_bar_gen = gen + 1;
        } else {
            while (*(volatile unsigned*)&g_bar_gen == gen) { }
        }
    }
    __syncthreads();
}

// ---------------- embedding gather ----------------
__global__ void embed_kernel(const int* __restrict__ tokens,
                             const float* __restrict__ emb,
                             float* __restrict__ x0) {
    int i = blockIdx.x * 256 + threadIdx.x;
    if (i >= BT * 128) return;
    int row = i >> 7;
    int c4  = (i & 127) << 2;
    int tok = tokens[row];
    *(float4*)&x0[row * 512 + c4] = *(const float4*)&emb[tok * 512 + c4];
}

// ---------------- SGEMM: C = A(MxK) @ W(KxN) + bias, f32x2, double-buffered ----------------
__global__ void __launch_bounds__(256, 2)
sgemm_bias(const float* __restrict__ A, const float* __restrict__ W,
           const float* __restrict__ bias, float* __restrict__ C,
           int M, int N, int K) {
    __shared__ float As_t[2][8][128];
    __shared__ float Bs2 [2][8][256];

    int tid = threadIdx.x;
    int bm = blockIdx.y * 128;
    int bn = blockIdx.x * 128;
    int tx = tid & 15, ty = tid >> 4;

    int a_row = tid >> 1;
    int a_col = (tid & 1) * 4;
    int b_row = tid >> 5;
    int b_col = (tid & 31) * 4;

    unsigned long long acc[4][8];
    #pragma unroll
    for (int i = 0; i < 4; i++)
        #pragma unroll
        for (int j = 0; j < 8; j++) acc[i][j] = 0ull;

    const float* Ap = A + (size_t)(bm + a_row) * K + a_col;
    const float* Wp = W + (size_t)b_row * N + bn + b_col;

    {
        float4 av = *(const float4*)(Ap);
        float4 bv = *(const float4*)(Wp);
        As_t[0][a_col + 0][a_row] = av.x;
        As_t[0][a_col + 1][a_row] = av.y;
        As_t[0][a_col + 2][a_row] = av.z;
        As_t[0][a_col + 3][a_row] = av.w;
        *(float2*)&Bs2[0][b_row][2 * (b_col + 0)] = make_float2(bv.x, bv.x);
        *(float2*)&Bs2[0][b_row][2 * (b_col + 1)] = make_float2(bv.y, bv.y);
        *(float2*)&Bs2[0][b_row][2 * (b_col + 2)] = make_float2(bv.z, bv.z);
        *(float2*)&Bs2[0][b_row][2 * (b_col + 3)] = make_float2(bv.w, bv.w);
    }
    __syncthreads();

    int cur = 0;
    for (int k0 = 8; k0 <= K; k0 += 8) {
        float4 av, bv;
        bool more = (k0 < K);
        if (more) {
            av = *(const float4*)(Ap + k0);
            bv = *(const float4*)(Wp + (size_t)k0 * N);
        }

        #pragma unroll
        for (int k = 0; k < 8; k++) {
            ulonglong2 A0 = *(const ulonglong2*)&As_t[cur][k][ty * 4];
            ulonglong2 A1 = *(const ulonglong2*)&As_t[cur][k][64 + ty * 4];
            ulonglong2 B0 = *(const ulonglong2*)&Bs2[cur][k][8 * tx];
            ulonglong2 B1 = *(const ulonglong2*)&Bs2[cur][k][8 * tx + 4];
            ulonglong2 B2 = *(const ulonglong2*)&Bs2[cur][k][128 + 8 * tx];
            ulonglong2 B3 = *(const ulonglong2*)&Bs2[cur][k][128 + 8 * tx + 4];
            unsigned long long ap[4] = {A0.x, A0.y, A1.x, A1.y};
            unsigned long long bp[8] = {B0.x, B0.y, B1.x, B1.y, B2.x, B2.y, B3.x, B3.y};
            #pragma unroll
            for (int rp = 0; rp < 4; rp++)
                #pragma unroll
                for (int cj = 0; cj < 8; cj++)
                    fma2(acc[rp][cj], ap[rp], bp[cj]);
        }

        if (more) {
            int nxt = cur ^ 1;
            As_t[nxt][a_col + 0][a_row] = av.x;
            As_t[nxt][a_col + 1][a_row] = av.y;
            As_t[nxt][a_col + 2][a_row] = av.z;
            As_t[nxt][a_col + 3][a_row] = av.w;
            *(float2*)&Bs2[nxt][b_row][2 * (b_col + 0)] = make_float2(bv.x, bv.x);
            *(float2*)&Bs2[nxt][b_row][2 * (b_col + 1)] = make_float2(bv.y, bv.y);
            *(float2*)&Bs2[nxt][b_row][2 * (b_col + 2)] = make_float2(bv.z, bv.z);
            *(float2*)&Bs2[nxt][b_row][2 * (b_col + 3)] = make_float2(bv.w, bv.w);
            __syncthreads();
            cur = nxt;
        }
    }

    float4 bs0 = *(const float4*)&bias[bn + tx * 4];
    float4 bs1 = *(const float4*)&bias[bn + 64 + tx * 4];
    float b0a[4] = {bs0.x, bs0.y, bs0.z, bs0.w};
    float b1a[4] = {bs1.x, bs1.y, bs1.z, bs1.w};

    #pragma unroll
    for (int rp = 0; rp < 4; rp++) {
        int r_lo = (rp < 2) ? (ty * 4 + rp * 2) : (64 + ty * 4 + (rp - 2) * 2);
        float2 v[8];
        #pragma unroll
        for (int cj = 0; cj < 8; cj++) v[cj] = up2(acc[rp][cj]);
        float4 o;
        float* Cr0 = C + (size_t)(bm + r_lo) * N;
        float* Cr1 = C + (size_t)(bm + r_lo + 1) * N;
        o = make_float4(v[0].x + b0a[0], v[1].x + b0a[1], v[2].x + b0a[2], v[3].x + b0a[3]);
        *(float4*)&Cr0[bn + tx * 4] = o;
        o = make_float4(v[0].y + b0a[0], v[1].y + b0a[1], v[2].y + b0a[2], v[3].y + b0a[3]);
        *(float4*)&Cr1[bn + tx * 4] = o;
        o = make_float4(v[4].x + b1a[0], v[5].x + b1a[1], v[6].x + b1a[2], v[7].x + b1a[3]);
        *(float4*)&Cr0[bn + 64 + tx * 4] = o;
        o = make_float4(v[4].y + b1a[0], v[5].y + b1a[1], v[6].y + b1a[2], v[7].y + b1a[3]);
        *(float4*)&Cr1[bn + 64 + tx * 4] = o;
    }
}

// ---------------- persistent bidirectional LSTM scan ----------------
// 128 blocks x 512 threads. dir = blockIdx>>6, unit slice u0 = (blockIdx&63)*8.
// Thread = (row, unit): row = tid>>3 (0..63), ul = tid&7. Per thread: 1 row x 4 gates.
// w_s: [256 kp][64] entry [kp][col*2+j] = Wh[2kp+j][gate*UU+u0+ulocal], col = ul*4+gate.
// h_s: [64 rows][HS2], k-contiguous. f32x2 accum lanes = (k even, k odd) partial sums.
__global__ void __launch_bounds__(512, 1)
lstm_scan(const float* __restrict__ xzf, const float* __restrict__ xzb,
          const float* __restrict__ Whf, const float* __restrict__ Whb,
          float* __restrict__ out, float* __restrict__ est_h, float* __restrict__ est_c) {
    extern __shared__ float sm[];
    float* w_s = sm;                 // [256][64]
    float* h_s = sm + 256 * 64;      // [64][HS2]

    int tid = threadIdx.x;
    int dir = blockIdx.x >> 6;
    int blk = blockIdx.x & 63;
    int u0  = blk * 8;
    const float* xz = dir ? xzb : xzf;
    const float* Wh = dir ? Whb : Whf;

    for (int i = tid; i < 256 * 64; i += 512) {
        int kp = i >> 6, c = i & 63;
        int col = c >> 1, j = c & 1;
        int ul2 = col >> 2, g = col & 3;
        w_s[i] = Wh[(size_t)(2 * kp + j) * GG + g * UU + u0 + ul2];
    }
    __syncthreads();

    int row = tid >> 3;
    int ul  = tid & 7;
    int u   = u0 + ul;

    const float* hr = &h_s[row * HS2];
    const float* wp = &w_s[ul * 8];

    float cc = 0.f;

    for (int t = 0; t < TT; t++) {
        int ttv = dir ? (TT - 1 - t) : t;

        // prefetch input projection for this step (in flight across staging)
        float z0[4];
        #pragma unroll
        for (int g = 0; g < 4; g++)
            z0[g] = xz[(size_t)(row * TT + ttv) * GG + g * UU + u];

        unsigned long long acc[4] = {0, 0, 0, 0};

        if (t > 0) {
            // stage h (row-major, L1 bypass); one warp covers exactly one row per instr
            const float* hg = g_h + ((t & 1) * 2 + dir) * (BB * UU);
            #pragma unroll 4
            for (int i = tid * 4; i < BB * UU; i += 2048) {
                float4 v = __ldcg((const float4*)(hg + i));
                *(float4*)&h_s[(i >> 9) * HS2 + (i & 511)] = v;
            }
            __syncthreads();

            #pragma unroll 8
            for (int kp = 0; kp < 256; kp++) {
                unsigned long long h2 = *(const unsigned long long*)(hr + 2 * kp);
                ulonglong2 wa = *(const ulonglong2*)(wp + kp * 64);
                ulonglong2 wb = *(const ulonglong2*)(wp + kp * 64 + 4);
                fma2(acc[0], h2, wa.x);
                fma2(acc[1], h2, wa.y);
                fma2(acc[2], h2, wb.x);
                fma2(acc[3], h2, wb.y);
            }
        }

        float zz[4];
        #pragma unroll
        for (int g = 0; g < 4; g++) {
            float2 p = up2(acc[g]);
            zz[g] = z0[g] + p.x + p.y;
        }

        float gi = sigf(zz[0]), gf = sigf(zz[1]);
        float gg = tanhf(zz[2]), go = sigf(zz[3]);
        cc = gf * cc + gi * gg;
        float hv = go * tanhf(cc);

        if (t + 1 < TT) {
            float* hn = g_h + (((t + 1) & 1) * 2 + dir) * (BB * UU);
            hn[row * UU + u] = hv;
        }

        out[(size_t)(row * TT + ttv) * 1024 + dir * UU + u] = hv;

        if (est_h != nullptr && t == TT - 1) {
            est_h[row * 1024 + dir * UU + u] = hv;
            est_c[row * 1024 + dir * UU + u] = cc;
        }

        if (t + 1 < TT) grid_barrier();
    }
}

// ---------------- launch ----------------
extern "C" void kernel_launch(void* const* d_in, const int* in_sizes, int n_in,
                              void* d_out, int out_size) {
    const int*   tokens = (const int*)  d_in[0];
    const float* emb    = (const float*)d_in[1];
    const float* Wx_f0 = (const float*)d_in[2];
    const float* Wh_f0 = (const float*)d_in[3];
    const float* b_f0  = (const float*)d_in[4];
    const float* Wx_b0 = (const float*)d_in[5];
    const float* Wh_b0 = (const float*)d_in[6];
    const float* b_b0  = (const float*)d_in[7];
    const float* Wx_f1 = (const float*)d_in[8];
    const float* Wh_f1 = (const float*)d_in[9];
    const float* b_f1  = (const float*)d_in[10];
    const float* Wx_b1 = (const float*)d_in[11];
    const float* Wh_b1 = (const float*)d_in[12];
    const float* b_b1  = (const float*)d_in[13];
    float* out = (float*)d_out;

    float *x0p, *y0p, *xzfp, *xzbp;
    cudaGetSymbolAddress((void**)&x0p,  g_x0);
    cudaGetSymbolAddress((void**)&y0p,  g_y0);
    cudaGetSymbolAddress((void**)&xzfp, g_xzf);
    cudaGetSymbolAddress((void**)&xzbp, g_xzb);

    cudaFuncSetAttribute(lstm_scan, cudaFuncAttributeMaxDynamicSharedMemorySize, SCAN_SMEM);

    embed_kernel<<<(BT * 128 + 255) / 256, 256>>>(tokens, emb, x0p);

    dim3 g0(GG / 128, BT / 128);
    sgemm_bias<<<g0, 256>>>(x0p, Wx_f0, b_f0, xzfp, BT, GG, 512);
    sgemm_bias<<<g0, 256>>>(x0p, Wx_b0, b_b0, xzbp, BT, GG, 512);

    lstm_scan<<<NBLK, 512, SCAN_SMEM>>>(xzfp, xzbp, Wh_f0, Wh_b0, y0p,
                                        (float*)nullptr, (float*)nullptr);

    sgemm_bias<<<g0, 256>>>(y0p, Wx_f1, b_f1, xzfp, BT, GG, 1024);
    sgemm_bias<<<g0, 256>>>(y0p, Wx_b1, b_b1, xzbp, BT, GG, 1024);

    float* est_h = out + (size_t)BT * 1024;
    float* est_c = est_h + BB * 1024;
    lstm_scan<<<NBLK, 512, SCAN_SMEM>>>(xzfp, xzbp, Wh_f1, Wh_b1, out, est_h, est_c);
}

// round 11
// speedup vs baseline: 1.8242x; 1.8242x over previous
#include <cuda_runtime.h>
#include <cstdint>

#define BB 64
#define TT 256
#define UU 512
#define GG 2048
#define BT (BB*TT)

#define NBLK 128
// smem floats: w_s 16384 | h_s 256*132=33792 | z_s 64*36=2304
#define WS_F   16384
#define HS_F   33792
#define ZS_F   2304
#define SCAN_SMEM ((WS_F + HS_F + ZS_F) * 4)   // 209920 B

// ---------------- static scratch ----------------
__device__ __align__(128) float g_x0 [BT * 512];
__device__ __align__(128) float g_y0 [BT * 1024];
__device__ __align__(128) float g_xzf[BT * GG];
__device__ __align__(128) float g_xzb[BT * GG];
// h exchange, k-pair packed + transposed: [buf][dir][kp][row][lane]
// region = 256 kp * 64 rows * 2 lanes = 32768 floats per (buf,dir)
__device__ __align__(128) float g_h2 [2 * 2 * 32768];
__device__ unsigned g_bar_count = 0;
__device__ unsigned g_bar_gen   = 0;

// ---------------- packed fp32 helpers ----------------
__device__ __forceinline__ void fma2(unsigned long long& d, unsigned long long a,
                                     unsigned long long b) {
    asm("fma.rn.f32x2 %0, %1, %2, %0;" : "+l"(d) : "l"(a), "l"(b));
}
__device__ __forceinline__ float2 up2(unsigned long long u) {
    float2 f; asm("mov.b64 {%0,%1}, %2;" : "=f"(f.x), "=f"(f.y) : "l"(u)); return f;
}
__device__ __forceinline__ float sigf(float x) { return 1.0f / (1.0f + expf(-x)); }

// R2-proven central grid barrier
__device__ __forceinline__ void grid_barrier() {
    __threadfence();
    __syncthreads();
    if (threadIdx.x == 0) {
        unsigned gen = *(volatile unsigned*)&g_bar_gen;
        if (atomicAdd(&g_bar_count, 1u) == NBLK - 1) {
            g_bar_count = 0;
            __threadfence();
            *(volatile unsigned*)&g_bar_gen = gen + 1;
        } else {
            while (*(volatile unsigned*)&g_bar_gen == gen) { }
        }
    }
    __syncthreads();
}

// ---------------- embedding gather ----------------
__global__ void embed_kernel(const int* __restrict__ tokens,
                             const float* __restrict__ emb,
                             float* __restrict__ x0) {
    int i = blockIdx.x * 256 + threadIdx.x;
    if (i >= BT * 128) return;
    int row = i >> 7;
    int c4  = (i & 127) << 2;
    int tok = tokens[row];
    *(float4*)&x0[row * 512 + c4] = *(const float4*)&emb[tok * 512 + c4];
}

// ---------------- SGEMM: C = A(MxK) @ W(KxN) + bias, f32x2, double-buffered ----------------
__global__ void __launch_bounds__(256, 2)
sgemm_bias(const float* __restrict__ A, const float* __restrict__ W,
           const float* __restrict__ bias, float* __restrict__ C,
           int M, int N, int K) {
    __shared__ float As_t[2][8][128];
    __shared__ float Bs2 [2][8][256];

    int tid = threadIdx.x;
    int bm = blockIdx.y * 128;
    int bn = blockIdx.x * 128;
    int tx = tid & 15, ty = tid >> 4;

    int a_row = tid >> 1;
    int a_col = (tid & 1) * 4;
    int b_row = tid >> 5;
    int b_col = (tid & 31) * 4;

    unsigned long long acc[4][8];
    #pragma unroll
    for (int i = 0; i < 4; i++)
        #pragma unroll
        for (int j = 0; j < 8; j++) acc[i][j] = 0ull;

    const float* Ap = A + (size_t)(bm + a_row) * K + a_col;
    const float* Wp = W + (size_t)b_row * N + bn + b_col;

    {
        float4 av = *(const float4*)(Ap);
        float4 bv = *(const float4*)(Wp);
        As_t[0][a_col + 0][a_row] = av.x;
        As_t[0][a_col + 1][a_row] = av.y;
        As_t[0][a_col + 2][a_row] = av.z;
        As_t[0][a_col + 3][a_row] = av.w;
        *(float2*)&Bs2[0][b_row][2 * (b_col + 0)] = make_float2(bv.x, bv.x);
        *(float2*)&Bs2[0][b_row][2 * (b_col + 1)] = make_float2(bv.y, bv.y);
        *(float2*)&Bs2[0][b_row][2 * (b_col + 2)] = make_float2(bv.z, bv.z);
        *(float2*)&Bs2[0][b_row][2 * (b_col + 3)] = make_float2(bv.w, bv.w);
    }
    __syncthreads();

    int cur = 0;
    for (int k0 = 8; k0 <= K; k0 += 8) {
        float4 av, bv;
        bool more = (k0 < K);
        if (more) {
            av = *(const float4*)(Ap + k0);
            bv = *(const float4*)(Wp + (size_t)k0 * N);
        }

        #pragma unroll
        for (int k = 0; k < 8; k++) {
            ulonglong2 A0 = *(const ulonglong2*)&As_t[cur][k][ty * 4];
            ulonglong2 A1 = *(const ulonglong2*)&As_t[cur][k][64 + ty * 4];
            ulonglong2 B0 = *(const ulonglong2*)&Bs2[cur][k][8 * tx];
            ulonglong2 B1 = *(const ulonglong2*)&Bs2[cur][k][8 * tx + 4];
            ulonglong2 B2 = *(const ulonglong2*)&Bs2[cur][k][128 + 8 * tx];
            ulonglong2 B3 = *(const ulonglong2*)&Bs2[cur][k][128 + 8 * tx + 4];
            unsigned long long ap[4] = {A0.x, A0.y, A1.x, A1.y};
            unsigned long long bp[8] = {B0.x, B0.y, B1.x, B1.y, B2.x, B2.y, B3.x, B3.y};
            #pragma unroll
            for (int rp = 0; rp < 4; rp++)
                #pragma unroll
                for (int cj = 0; cj < 8; cj++)
                    fma2(acc[rp][cj], ap[rp], bp[cj]);
        }

        if (more) {
            int nxt = cur ^ 1;
            As_t[nxt][a_col + 0][a_row] = av.x;
            As_t[nxt][a_col + 1][a_row] = av.y;
            As_t[nxt][a_col + 2][a_row] = av.z;
            As_t[nxt][a_col + 3][a_row] = av.w;
            *(float2*)&Bs2[nxt][b_row][2 * (b_col + 0)] = make_float2(bv.x, bv.x);
            *(float2*)&Bs2[nxt][b_row][2 * (b_col + 1)] = make_float2(bv.y, bv.y);
            *(float2*)&Bs2[nxt][b_row][2 * (b_col + 2)] = make_float2(bv.z, bv.z);
            *(float2*)&Bs2[nxt][b_row][2 * (b_col + 3)] = make_float2(bv.w, bv.w);
            __syncthreads();
            cur = nxt;
        }
    }

    float4 bs0 = *(const float4*)&bias[bn + tx * 4];
    float4 bs1 = *(const float4*)&bias[bn + 64 + tx * 4];
    float b0a[4] = {bs0.x, bs0.y, bs0.z, bs0.w};
    float b1a[4] = {bs1.x, bs1.y, bs1.z, bs1.w};

    #pragma unroll
    for (int rp = 0; rp < 4; rp++) {
        int r_lo = (rp < 2) ? (ty * 4 + rp * 2) : (64 + ty * 4 + (rp - 2) * 2);
        float2 v[8];
        #pragma unroll
        for (int cj = 0; cj < 8; cj++) v[cj] = up2(acc[rp][cj]);
        float4 o;
        float* Cr0 = C + (size_t)(bm + r_lo) * N;
        float* Cr1 = C + (size_t)(bm + r_lo + 1) * N;
        o = make_float4(v[0].x + b0a[0], v[1].x + b0a[1], v[2].x + b0a[2], v[3].x + b0a[3]);
        *(float4*)&Cr0[bn + tx * 4] = o;
        o = make_float4(v[0].y + b0a[0], v[1].y + b0a[1], v[2].y + b0a[2], v[3].y + b0a[3]);
        *(float4*)&Cr1[bn + tx * 4] = o;
        o = make_float4(v[4].x + b1a[0], v[5].x + b1a[1], v[6].x + b1a[2], v[7].x + b1a[3]);
        *(float4*)&Cr0[bn + 64 + tx * 4] = o;
        o = make_float4(v[4].y + b1a[0], v[5].y + b1a[1], v[6].y + b1a[2], v[7].y + b1a[3]);
        *(float4*)&Cr1[bn + 64 + tx * 4] = o;
    }
}

// ---------------- persistent bidirectional LSTM scan (register-tiled GEMM) ----------------
// 128 blocks x 256 threads. dir = blockIdx>>6, unit slice u0 = (blockIdx&63)*8.
// GEMM phase: thread (tx=tid&15, ty=tid>>4) computes rows 4ty..4ty+3 x cols 2tx,2tx+1
//   of the 64x32 z-tile; f32x2 lanes = (k even, k odd).
//   w_s[kp*64 + c*2 + j] = Wh[2kp+j][g*512 + u0 + ul], c = ul*4+g.
//   h_s[kp*132 + row*2 + lane] = h[2kp+lane][row]  (g_h2 mirrors this, unpadded: kp*128).
// Elementwise phase: thread owns cells (erow, eul) and (erow+32, eul); c-state in regs.
__global__ void __launch_bounds__(256, 1)
lstm_scan(const float* __restrict__ xzf, const float* __restrict__ xzb,
          const float* __restrict__ Whf, const float* __restrict__ Whb,
          float* __restrict__ out, float* __restrict__ est_h, float* __restrict__ est_c) {
    extern __shared__ float sm[];
    float* w_s = sm;                     // 16384 floats
    float* h_s = sm + WS_F;              // 33792 floats
    float* z_s = sm + WS_F + HS_F;       // 2304 floats, stride 36 per row

    int tid = threadIdx.x;
    int dir = blockIdx.x >> 6;
    int u0  = (blockIdx.x & 63) * 8;
    const float* xz = dir ? xzb : xzf;
    const float* Wh = dir ? Whb : Whf;

    // stage Wh slice (once)
    for (int i = tid; i < WS_F; i += 256) {
        int kp = i >> 6, rem = i & 63;
        int c = rem >> 1, j = rem & 1;
        int ul = c >> 2, g = c & 3;
        w_s[i] = Wh[(size_t)(2 * kp + j) * GG + g * UU + u0 + ul];
    }
    __syncthreads();

    int tx = tid & 15, ty = tid >> 4;
    const float* hp = h_s + 8 * ty;      // + kp*132
    const float* wq = w_s + 4 * tx;      // + kp*64

    int erow = tid >> 3;                 // 0..31 (second cell: erow+32)
    int eul  = tid & 7;
    int eu   = u0 + eul;
    int ekp  = eu >> 1, elane = eu & 1;

    float cc0 = 0.f, cc1 = 0.f;

    for (int t = 0; t < TT; t++) {
        int ttv = dir ? (TT - 1 - t) : t;

        // prefetch input projections (elementwise mapping; overlap staging+GEMM)
        float z0a[4], z0b[4];
        #pragma unroll
        for (int g = 0; g < 4; g++) {
            z0a[g] = xz[(size_t)(erow * TT + ttv) * GG + g * UU + eu];
            z0b[g] = xz[(size_t)((erow + 32) * TT + ttv) * GG + g * UU + eu];
        }

        if (t > 0) {
            // stage full h (32768 floats): straight coalesced copy with stride pad
            const float* hg = g_h2 + ((t & 1) * 2 + dir) * 32768;
            #pragma unroll 4
            for (int i = tid * 4; i < 32768; i += 1024) {
                float4 v = __ldcg((const float4*)(hg + i));
                *(float4*)&h_s[(i >> 7) * 132 + (i & 127)] = v;
            }
            __syncthreads();

            unsigned long long acc[4][2] = {{0,0},{0,0},{0,0},{0,0}};
            #pragma unroll 8
            for (int kp = 0; kp < 256; kp++) {
                ulonglong2 ha = *(const ulonglong2*)(hp + kp * 132);      // rows 4ty,4ty+1
                ulonglong2 hb = *(const ulonglong2*)(hp + kp * 132 + 4);  // rows 4ty+2,4ty+3
                ulonglong2 wv = *(const ulonglong2*)(wq + kp * 64);       // cols 2tx,2tx+1
                fma2(acc[0][0], ha.x, wv.x); fma2(acc[0][1], ha.x, wv.y);
                fma2(acc[1][0], ha.y, wv.x); fma2(acc[1][1], ha.y, wv.y);
                fma2(acc[2][0], hb.x, wv.x); fma2(acc[2][1], hb.x, wv.y);
                fma2(acc[3][0], hb.y, wv.x); fma2(acc[3][1], hb.y, wv.y);
            }

            #pragma unroll
            for (int r = 0; r < 4; r++) {
                float2 pa = up2(acc[r][0]);
                float2 pb = up2(acc[r][1]);
                *(float2*)&z_s[(4 * ty + r) * 36 + 2 * tx] =
                    make_float2(pa.x + pa.y, pb.x + pb.y);
            }
        }
        __syncthreads();

        float4 zr0 = make_float4(0.f, 0.f, 0.f, 0.f);
        float4 zr1 = make_float4(0.f, 0.f, 0.f, 0.f);
        if (t > 0) {
            zr0 = *(const float4*)&z_s[erow * 36 + eul * 4];
            zr1 = *(const float4*)&z_s[(erow + 32) * 36 + eul * 4];
        }

        float gi0 = sigf(z0a[0] + zr0.x), gf0 = sigf(z0a[1] + zr0.y);
        float gg0 = tanhf(z0a[2] + zr0.z), go0 = sigf(z0a[3] + zr0.w);
        cc0 = gf0 * cc0 + gi0 * gg0;
        float h0 = go0 * tanhf(cc0);

        float gi1 = sigf(z0b[0] + zr1.x), gf1 = sigf(z0b[1] + zr1.y);
        float gg1 = tanhf(z0b[2] + zr1.z), go1 = sigf(z0b[3] + zr1.w);
        cc1 = gf1 * cc1 + gi1 * gg1;
        float h1 = go1 * tanhf(cc1);

        if (t + 1 < TT) {
            float* hn = g_h2 + (((t + 1) & 1) * 2 + dir) * 32768;
            hn[ekp * 128 + erow * 2 + elane]        = h0;
            hn[ekp * 128 + (erow + 32) * 2 + elane] = h1;
        }

        out[(size_t)(erow * TT + ttv) * 1024 + dir * UU + eu]        = h0;
        out[(size_t)((erow + 32) * TT + ttv) * 1024 + dir * UU + eu] = h1;

        if (est_h != nullptr && t == TT - 1) {
            est_h[erow * 1024 + dir * UU + eu]        = h0;
            est_h[(erow + 32) * 1024 + dir * UU + eu] = h1;
            est_c[erow * 1024 + dir * UU + eu]        = cc0;
            est_c[(erow + 32) * 1024 + dir * UU + eu] = cc1;
        }

        if (t + 1 < TT) grid_barrier();
    }
}

// ---------------- launch ----------------
extern "C" void kernel_launch(void* const* d_in, const int* in_sizes, int n_in,
                              void* d_out, int out_size) {
    const int*   tokens = (const int*)  d_in[0];
    const float* emb    = (const float*)d_in[1];
    const float* Wx_f0 = (const float*)d_in[2];
    const float* Wh_f0 = (const float*)d_in[3];
    const float* b_f0  = (const float*)d_in[4];
    const float* Wx_b0 = (const float*)d_in[5];
    const float* Wh_b0 = (const float*)d_in[6];
    const float* b_b0  = (const float*)d_in[7];
    const float* Wx_f1 = (const float*)d_in[8];
    const float* Wh_f1 = (const float*)d_in[9];
    const float* b_f1  = (const float*)d_in[10];
    const float* Wx_b1 = (const float*)d_in[11];
    const float* Wh_b1 = (const float*)d_in[12];
    const float* b_b1  = (const float*)d_in[13];
    float* out = (float*)d_out;

    float *x0p, *y0p, *xzfp, *xzbp;
    cudaGetSymbolAddress((void**)&x0p,  g_x0);
    cudaGetSymbolAddress((void**)&y0p,  g_y0);
    cudaGetSymbolAddress((void**)&xzfp, g_xzf);
    cudaGetSymbolAddress((void**)&xzbp, g_xzb);

    cudaFuncSetAttribute(lstm_scan, cudaFuncAttributeMaxDynamicSharedMemorySize, SCAN_SMEM);

    embed_kernel<<<(BT * 128 + 255) / 256, 256>>>(tokens, emb, x0p);

    dim3 g0(GG / 128, BT / 128);
    sgemm_bias<<<g0, 256>>>(x0p, Wx_f0, b_f0, xzfp, BT, GG, 512);
    sgemm_bias<<<g0, 256>>>(x0p, Wx_b0, b_b0, xzbp, BT, GG, 512);

    lstm_scan<<<NBLK, 256, SCAN_SMEM>>>(xzfp, xzbp, Wh_f0, Wh_b0, y0p,
                                        (float*)nullptr, (float*)nullptr);

    sgemm_bias<<<g0, 256>>>(y0p, Wx_f1, b_f1, xzfp, BT, GG, 1024);
    sgemm_bias<<<g0, 256>>>(y0p, Wx_b1, b_b1, xzbp, BT, GG, 1024);

    float* est_h = out + (size_t)BT * 1024;
    float* est_c = est_h + BB * 1024;
    lstm_scan<<<NBLK, 256, SCAN_SMEM>>>(xzfp, xzbp, Wh_f1, Wh_b1, out, est_h, est_c);
}

// round 12
// speedup vs baseline: 1.8762x; 1.0285x over previous
#include <cuda_runtime.h>
#include <cstdint>

#define BB 64
#define TT 256
#define UU 512
#define GG 2048
#define BT (BB*TT)

#define NBLK 128
// smem floats: w_s 16384 | h_s 256*132=33792 | z_s 64*36=2304
#define WS_F   16384
#define HS_F   33792
#define ZS_F   2304
#define SCAN_SMEM ((WS_F + HS_F + ZS_F) * 4)   // 209920 B

// ---------------- static scratch ----------------
__device__ __align__(128) float g_x0 [BT * 512];
__device__ __align__(128) float g_y0 [BT * 1024];
__device__ __align__(128) float g_xzf[BT * GG];
__device__ __align__(128) float g_xzb[BT * GG];
// h exchange, k-pair packed + transposed: [buf][dir][kp][row][lane]
// region = 256 kp * 64 rows * 2 lanes = 32768 floats per (buf,dir)
__device__ __align__(128) float g_h2 [2 * 2 * 32768];
// 8-way distributed monotonic arrival counters (memset before each scan launch)
__device__ __align__(128) unsigned g_cnt[8];

// ---------------- packed fp32 helpers ----------------
__device__ __forceinline__ void fma2(unsigned long long& d, unsigned long long a,
                                     unsigned long long b) {
    asm("fma.rn.f32x2 %0, %1, %2, %0;" : "+l"(d) : "l"(a), "l"(b));
}
__device__ __forceinline__ float2 up2(unsigned long long u) {
    float2 f; asm("mov.b64 {%0,%1}, %2;" : "=f"(f.x), "=f"(f.y) : "l"(u)); return f;
}
__device__ __forceinline__ float sigf(float x) { return 1.0f / (1.0f + expf(-x)); }

// ---------------- embedding gather ----------------
__global__ void embed_kernel(const int* __restrict__ tokens,
                             const float* __restrict__ emb,
                             float* __restrict__ x0) {
    int i = blockIdx.x * 256 + threadIdx.x;
    if (i >= BT * 128) return;
    int row = i >> 7;
    int c4  = (i & 127) << 2;
    int tok = tokens[row];
    *(float4*)&x0[row * 512 + c4] = *(const float4*)&emb[tok * 512 + c4];
}

// ---------------- SGEMM: C = A(MxK) @ W(KxN) + bias, f32x2, double-buffered ----------------
__global__ void __launch_bounds__(256, 2)
sgemm_bias(const float* __restrict__ A, const float* __restrict__ W,
           const float* __restrict__ bias, float* __restrict__ C,
           int M, int N, int K) {
    __shared__ float As_t[2][8][128];
    __shared__ float Bs2 [2][8][256];

    int tid = threadIdx.x;
    int bm = blockIdx.y * 128;
    int bn = blockIdx.x * 128;
    int tx = tid & 15, ty = tid >> 4;

    int a_row = tid >> 1;
    int a_col = (tid & 1) * 4;
    int b_row = tid >> 5;
    int b_col = (tid & 31) * 4;

    unsigned long long acc[4][8];
    #pragma unroll
    for (int i = 0; i < 4; i++)
        #pragma unroll
        for (int j = 0; j < 8; j++) acc[i][j] = 0ull;

    const float* Ap = A + (size_t)(bm + a_row) * K + a_col;
    const float* Wp = W + (size_t)b_row * N + bn + b_col;

    {
        float4 av = *(const float4*)(Ap);
        float4 bv = *(const float4*)(Wp);
        As_t[0][a_col + 0][a_row] = av.x;
        As_t[0][a_col + 1][a_row] = av.y;
        As_t[0][a_col + 2][a_row] = av.z;
        As_t[0][a_col + 3][a_row] = av.w;
        *(float2*)&Bs2[0][b_row][2 * (b_col + 0)] = make_float2(bv.x, bv.x);
        *(float2*)&Bs2[0][b_row][2 * (b_col + 1)] = make_float2(bv.y, bv.y);
        *(float2*)&Bs2[0][b_row][2 * (b_col + 2)] = make_float2(bv.z, bv.z);
        *(float2*)&Bs2[0][b_row][2 * (b_col + 3)] = make_float2(bv.w, bv.w);
    }
    __syncthreads();

    int cur = 0;
    for (int k0 = 8; k0 <= K; k0 += 8) {
        float4 av, bv;
        bool more = (k0 < K);
        if (more) {
            av = *(const float4*)(Ap + k0);
            bv = *(const float4*)(Wp + (size_t)k0 * N);
        }

        #pragma unroll
        for (int k = 0; k < 8; k++) {
            ulonglong2 A0 = *(const ulonglong2*)&As_t[cur][k][ty * 4];
            ulonglong2 A1 = *(const ulonglong2*)&As_t[cur][k][64 + ty * 4];
            ulonglong2 B0 = *(const ulonglong2*)&Bs2[cur][k][8 * tx];
            ulonglong2 B1 = *(const ulonglong2*)&Bs2[cur][k][8 * tx + 4];
            ulonglong2 B2 = *(const ulonglong2*)&Bs2[cur][k][128 + 8 * tx];
            ulonglong2 B3 = *(const ulonglong2*)&Bs2[cur][k][128 + 8 * tx + 4];
            unsigned long long ap[4] = {A0.x, A0.y, A1.x, A1.y};
            unsigned long long bp[8] = {B0.x, B0.y, B1.x, B1.y, B2.x, B2.y, B3.x, B3.y};
            #pragma unroll
            for (int rp = 0; rp < 4; rp++)
                #pragma unroll
                for (int cj = 0; cj < 8; cj++)
                    fma2(acc[rp][cj], ap[rp], bp[cj]);
        }

        if (more) {
            int nxt = cur ^ 1;
            As_t[nxt][a_col + 0][a_row] = av.x;
            As_t[nxt][a_col + 1][a_row] = av.y;
            As_t[nxt][a_col + 2][a_row] = av.z;
            As_t[nxt][a_col + 3][a_row] = av.w;
            *(float2*)&Bs2[nxt][b_row][2 * (b_col + 0)] = make_float2(bv.x, bv.x);
            *(float2*)&Bs2[nxt][b_row][2 * (b_col + 1)] = make_float2(bv.y, bv.y);
            *(float2*)&Bs2[nxt][b_row][2 * (b_col + 2)] = make_float2(bv.z, bv.z);
            *(float2*)&Bs2[nxt][b_row][2 * (b_col + 3)] = make_float2(bv.w, bv.w);
            __syncthreads();
            cur = nxt;
        }
    }

    float4 bs0 = *(const float4*)&bias[bn + tx * 4];
    float4 bs1 = *(const float4*)&bias[bn + 64 + tx * 4];
    float b0a[4] = {bs0.x, bs0.y, bs0.z, bs0.w};
    float b1a[4] = {bs1.x, bs1.y, bs1.z, bs1.w};

    #pragma unroll
    for (int rp = 0; rp < 4; rp++) {
        int r_lo = (rp < 2) ? (ty * 4 + rp * 2) : (64 + ty * 4 + (rp - 2) * 2);
        float2 v[8];
        #pragma unroll
        for (int cj = 0; cj < 8; cj++) v[cj] = up2(acc[rp][cj]);
        float4 o;
        float* Cr0 = C + (size_t)(bm + r_lo) * N;
        float* Cr1 = C + (size_t)(bm + r_lo + 1) * N;
        o = make_float4(v[0].x + b0a[0], v[1].x + b0a[1], v[2].x + b0a[2], v[3].x + b0a[3]);
        *(float4*)&Cr0[bn + tx * 4] = o;
        o = make_float4(v[0].y + b0a[0], v[1].y + b0a[1], v[2].y + b0a[2], v[3].y + b0a[3]);
        *(float4*)&Cr1[bn + tx * 4] = o;
        o = make_float4(v[4].x + b1a[0], v[5].x + b1a[1], v[6].x + b1a[2], v[7].x + b1a[3]);
        *(float4*)&Cr0[bn + 64 + tx * 4] = o;
        o = make_float4(v[4].y + b1a[0], v[5].y + b1a[1], v[6].y + b1a[2], v[7].y + b1a[3]);
        *(float4*)&Cr1[bn + 64 + tx * 4] = o;
    }
}

// ---------------- persistent bidirectional LSTM scan (register-tiled, split barrier) ----------------
// 128 blocks x 256 threads. dir = blockIdx>>6, unit slice u0 = (blockIdx&63)*8.
// GEMM: thread (tx,ty) computes rows 4ty..4ty+3 x cols 2tx,2tx+1 of the 64x32 z-tile.
// Sync: split arrive/wait. Arrive: fence; syncthreads; tid0 atomicAdd(g_cnt[blk&7]).
//       Wait (next iter, AFTER out-stores + z-prefetch): tid 0..7 acquire-poll
//       g_cnt[tid] until >= 16*t. Counters monotonic; memset per launch.
// Skew bound 1 step => double-buffered g_h2 is safe (same proof as monolithic barrier).
__global__ void __launch_bounds__(256, 1)
lstm_scan(const float* __restrict__ xzf, const float* __restrict__ xzb,
          const float* __restrict__ Whf, const float* __restrict__ Whb,
          float* __restrict__ out, float* __restrict__ est_h, float* __restrict__ est_c) {
    extern __shared__ float sm[];
    float* w_s = sm;                     // 16384 floats
    float* h_s = sm + WS_F;              // 33792 floats
    float* z_s = sm + WS_F + HS_F;       // 2304 floats, stride 36 per row

    int tid = threadIdx.x;
    int dir = blockIdx.x >> 6;
    int u0  = (blockIdx.x & 63) * 8;
    unsigned* my_cnt = &g_cnt[blockIdx.x & 7];
    const float* xz = dir ? xzb : xzf;
    const float* Wh = dir ? Whb : Whf;

    // stage Wh slice (once)
    for (int i = tid; i < WS_F; i += 256) {
        int kp = i >> 6, rem = i & 63;
        int c = rem >> 1, j = rem & 1;
        int ul = c >> 2, g = c & 3;
        w_s[i] = Wh[(size_t)(2 * kp + j) * GG + g * UU + u0 + ul];
    }
    __syncthreads();

    int tx = tid & 15, ty = tid >> 4;
    const float* hp = h_s + 8 * ty;      // + kp*132
    const float* wq = w_s + 4 * tx;      // + kp*64

    int erow = tid >> 3;                 // 0..31 (second cell: erow+32)
    int eul  = tid & 7;
    int eu   = u0 + eul;
    int ekp  = eu >> 1, elane = eu & 1;

    float cc0 = 0.f, cc1 = 0.f;

    for (int t = 0; t < TT; t++) {
        int ttv = dir ? (TT - 1 - t) : t;

        // prefetch input projections (issued BEFORE the wait: in flight across the poll)
        float z0a[4], z0b[4];
        #pragma unroll
        for (int g = 0; g < 4; g++) {
            z0a[g] = xz[(size_t)(erow * TT + ttv) * GG + g * UU + eu];
            z0b[g] = xz[(size_t)((erow + 32) * TT + ttv) * GG + g * UU + eu];
        }

        if (t > 0) {
            // wait: all 128 blocks arrived for step t-1 (each counter reaches 16*t)
            if (tid < 8) {
                const unsigned* f = &g_cnt[tid];
                unsigned target = 16u * (unsigned)t;
                unsigned v;
                do {
                    asm volatile("ld.acquire.gpu.u32 %0, [%1];" : "=r"(v) : "l"(f));
                } while (v < target);
            }
            __syncthreads();

            // stage full h (32768 floats): straight coalesced copy with stride pad
            const float* hg = g_h2 + ((t & 1) * 2 + dir) * 32768;
            #pragma unroll 4
            for (int i = tid * 4; i < 32768; i += 1024) {
                float4 v = __ldcg((const float4*)(hg + i));
                *(float4*)&h_s[(i >> 7) * 132 + (i & 127)] = v;
            }
            __syncthreads();

            unsigned long long acc[4][2] = {{0,0},{0,0},{0,0},{0,0}};
            #pragma unroll 8
            for (int kp = 0; kp < 256; kp++) {
                ulonglong2 ha = *(const ulonglong2*)(hp + kp * 132);      // rows 4ty,4ty+1
                ulonglong2 hb = *(const ulonglong2*)(hp + kp * 132 + 4);  // rows 4ty+2,4ty+3
                ulonglong2 wv = *(const ulonglong2*)(wq + kp * 64);       // cols 2tx,2tx+1
                fma2(acc[0][0], ha.x, wv.x); fma2(acc[0][1], ha.x, wv.y);
                fma2(acc[1][0], ha.y, wv.x); fma2(acc[1][1], ha.y, wv.y);
                fma2(acc[2][0], hb.x, wv.x); fma2(acc[2][1], hb.x, wv.y);
                fma2(acc[3][0], hb.y, wv.x); fma2(acc[3][1], hb.y, wv.y);
            }

            #pragma unroll
            for (int r = 0; r < 4; r++) {
                float2 pa = up2(acc[r][0]);
                float2 pb = up2(acc[r][1]);
                *(float2*)&z_s[(4 * ty + r) * 36 + 2 * tx] =
                    make_float2(pa.x + pa.y, pb.x + pb.y);
            }
        }
        __syncthreads();

        float4 zr0 = make_float4(0.f, 0.f, 0.f, 0.f);
        float4 zr1 = make_float4(0.f, 0.f, 0.f, 0.f);
        if (t > 0) {
            zr0 = *(const float4*)&z_s[erow * 36 + eul * 4];
            zr1 = *(const float4*)&z_s[(erow + 32) * 36 + eul * 4];
        }

        float gi0 = sigf(z0a[0] + zr0.x), gf0 = sigf(z0a[1] + zr0.y);
        float gg0 = tanhf(z0a[2] + zr0.z), go0 = sigf(z0a[3] + zr0.w);
        cc0 = gf0 * cc0 + gi0 * gg0;
        float h0 = go0 * tanhf(cc0);

        float gi1 = sigf(z0b[0] + zr1.x), gf1 = sigf(z0b[1] + zr1.y);
        float gg1 = tanhf(z0b[2] + zr1.z), go1 = sigf(z0b[3] + zr1.w);
        cc1 = gf1 * cc1 + gi1 * gg1;
        float h1 = go1 * tanhf(cc1);

        bool not_last = (t + 1 < TT);
        if (not_last) {
            // publish h, then arrive (as early as possible)
            float* hn = g_h2 + (((t + 1) & 1) * 2 + dir) * 32768;
            hn[ekp * 128 + erow * 2 + elane]        = h0;
            hn[ekp * 128 + (erow + 32) * 2 + elane] = h1;
            __threadfence();
            __syncthreads();
            if (tid == 0) atomicAdd(my_cnt, 1u);
        }

        // these overlap other blocks' arrivals (wait happens next iteration)
        out[(size_t)(erow * TT + ttv) * 1024 + dir * UU + eu]        = h0;
        out[(size_t)((erow + 32) * TT + ttv) * 1024 + dir * UU + eu] = h1;

        if (est_h != nullptr && t == TT - 1) {
            est_h[erow * 1024 + dir * UU + eu]        = h0;
            est_h[(erow + 32) * 1024 + dir * UU + eu] = h1;
            est_c[erow * 1024 + dir * UU + eu]        = cc0;
            est_c[(erow + 32) * 1024 + dir * UU + eu] = cc1;
        }
    }
}

// ---------------- launch ----------------
extern "C" void kernel_launch(void* const* d_in, const int* in_sizes, int n_in,
                              void* d_out, int out_size) {
    const int*   tokens = (const int*)  d_in[0];
    const float* emb    = (const float*)d_in[1];
    const float* Wx_f0 = (const float*)d_in[2];
    const float* Wh_f0 = (const float*)d_in[3];
    const float* b_f0  = (const float*)d_in[4];
    const float* Wx_b0 = (const float*)d_in[5];
    const float* Wh_b0 = (const float*)d_in[6];
    const float* b_b0  = (const float*)d_in[7];
    const float* Wx_f1 = (const float*)d_in[8];
    const float* Wh_f1 = (const float*)d_in[9];
    const float* b_f1  = (const float*)d_in[10];
    const float* Wx_b1 = (const float*)d_in[11];
    const float* Wh_b1 = (const float*)d_in[12];
    const float* b_b1  = (const float*)d_in[13];
    float* out = (float*)d_out;

    float *x0p, *y0p, *xzfp, *xzbp;
    void* cntp;
    cudaGetSymbolAddress((void**)&x0p,  g_x0);
    cudaGetSymbolAddress((void**)&y0p,  g_y0);
    cudaGetSymbolAddress((void**)&xzfp, g_xzf);
    cudaGetSymbolAddress((void**)&xzbp, g_xzb);
    cudaGetSymbolAddress(&cntp, g_cnt);

    cudaFuncSetAttribute(lstm_scan, cudaFuncAttributeMaxDynamicSharedMemorySize, SCAN_SMEM);

    embed_kernel<<<(BT * 128 + 255) / 256, 256>>>(tokens, emb, x0p);

    dim3 g0(GG / 128, BT / 128);
    sgemm_bias<<<g0, 256>>>(x0p, Wx_f0, b_f0, xzfp, BT, GG, 512);
    sgemm_bias<<<g0, 256>>>(x0p, Wx_b0, b_b0, xzbp, BT, GG, 512);

    cudaMemsetAsync(cntp, 0, 8 * sizeof(unsigned));
    lstm_scan<<<NBLK, 256, SCAN_SMEM>>>(xzfp, xzbp, Wh_f0, Wh_b0, y0p,
                                        (float*)nullptr, (float*)nullptr);

    sgemm_bias<<<g0, 256>>>(y0p, Wx_f1, b_f1, xzfp, BT, GG, 1024);
    sgemm_bias<<<g0, 256>>>(y0p, Wx_b1, b_b1, xzbp, BT, GG, 1024);

    float* est_h = out + (size_t)BT * 1024;
    float* est_c = est_h + BB * 1024;
    cudaMemsetAsync(cntp, 0, 8 * sizeof(unsigned));
    lstm_scan<<<NBLK, 256, SCAN_SMEM>>>(xzfp, xzbp, Wh_f1, Wh_b1, out, est_h, est_c);
}

// round 13
// speedup vs baseline: 2.3813x; 1.2693x over previous
#include <cuda_runtime.h>
#include <cstdint>

#define BB 64
#define TT 256
#define UU 512
#define GG 2048
#define BT (BB*TT)

#define NBLK 128
// smem floats: w_s 16384 | h_s 256*132=33792 | z_s 64*36=2304
#define WS_F   16384
#define HS_F   33792
#define ZS_F   2304
#define SCAN_SMEM ((WS_F + HS_F + ZS_F) * 4)   // 209920 B

// ---------------- static scratch ----------------
__device__ __align__(128) float g_x0 [BT * 512];
__device__ __align__(128) float g_y0 [BT * 1024];
__device__ __align__(128) float g_xzf[BT * GG];
__device__ __align__(128) float g_xzb[BT * GG];
// h exchange, k-pair packed + transposed: [buf][dir][kp][row][lane]
__device__ __align__(128) float g_h2 [2 * 2 * 32768];
// 8-way distributed monotonic arrival counters (memset before each scan launch)
__device__ __align__(128) unsigned g_cnt[8];

// ---------------- packed fp32 helpers ----------------
__device__ __forceinline__ void fma2(unsigned long long& d, unsigned long long a,
                                     unsigned long long b) {
    asm("fma.rn.f32x2 %0, %1, %2, %0;" : "+l"(d) : "l"(a), "l"(b));
}
__device__ __forceinline__ float2 up2(unsigned long long u) {
    float2 f; asm("mov.b64 {%0,%1}, %2;" : "=f"(f.x), "=f"(f.y) : "l"(u)); return f;
}
__device__ __forceinline__ float sigf(float x) { return 1.0f / (1.0f + expf(-x)); }

// ---------------- embedding gather ----------------
__global__ void embed_kernel(const int* __restrict__ tokens,
                             const float* __restrict__ emb,
                             float* __restrict__ x0) {
    int i = blockIdx.x * 256 + threadIdx.x;
    if (i >= BT * 128) return;
    int row = i >> 7;
    int c4  = (i & 127) << 2;
    int tok = tokens[row];
    *(float4*)&x0[row * 512 + c4] = *(const float4*)&emb[tok * 512 + c4];
}

// ---------------- SGEMM: C = A(MxK) @ W(KxN) + bias ----------------
// f32x2 lanes = adjacent COLUMNS; A duplicated in smem (broadcast loads),
// B contiguous in smem (coalesced loads). Double-buffered.
__global__ void __launch_bounds__(256, 2)
sgemm_bias(const float* __restrict__ A, const float* __restrict__ W,
           const float* __restrict__ bias, float* __restrict__ C,
           int M, int N, int K) {
    __shared__ float As2[2][8][256];   // [buf][k][2*row+lane] (dup)
    __shared__ float Bs [2][8][128];   // [buf][k][col]

    int tid = threadIdx.x;
    int bm = blockIdx.y * 128;
    int bn = blockIdx.x * 128;
    int tx = tid & 15, ty = tid >> 4;

    int a_row = tid >> 1;
    int a_col = (tid & 1) * 4;
    int b_row = tid >> 5;
    int b_col = (tid & 31) * 4;

    unsigned long long acc[8][4];
    #pragma unroll
    for (int i = 0; i < 8; i++)
        #pragma unroll
        for (int j = 0; j < 4; j++) acc[i][j] = 0ull;

    const float* Ap = A + (size_t)(bm + a_row) * K + a_col;
    const float* Wp = W + (size_t)b_row * N + bn + b_col;

    {
        float4 av = *(const float4*)(Ap);
        float4 bv = *(const float4*)(Wp);
        *(float2*)&As2[0][a_col + 0][2 * a_row] = make_float2(av.x, av.x);
        *(float2*)&As2[0][a_col + 1][2 * a_row] = make_float2(av.y, av.y);
        *(float2*)&As2[0][a_col + 2][2 * a_row] = make_float2(av.z, av.z);
        *(float2*)&As2[0][a_col + 3][2 * a_row] = make_float2(av.w, av.w);
        *(float4*)&Bs[0][b_row][b_col] = bv;
    }
    __syncthreads();

    int cur = 0;
    for (int k0 = 8; k0 <= K; k0 += 8) {
        float4 av, bv;
        bool more = (k0 < K);
        if (more) {
            av = *(const float4*)(Ap + k0);
            bv = *(const float4*)(Wp + (size_t)k0 * N);
        }

        #pragma unroll
        for (int k = 0; k < 8; k++) {
            ulonglong2 A0 = *(const ulonglong2*)&As2[cur][k][2 * (ty * 4)];
            ulonglong2 A1 = *(const ulonglong2*)&As2[cur][k][2 * (ty * 4 + 2)];
            ulonglong2 A2 = *(const ulonglong2*)&As2[cur][k][2 * (64 + ty * 4)];
            ulonglong2 A3 = *(const ulonglong2*)&As2[cur][k][2 * (64 + ty * 4 + 2)];
            ulonglong2 B0 = *(const ulonglong2*)&Bs[cur][k][4 * tx];
            ulonglong2 B1 = *(const ulonglong2*)&Bs[cur][k][64 + 4 * tx];
            unsigned long long ap[8] = {A0.x, A0.y, A1.x, A1.y, A2.x, A2.y, A3.x, A3.y};
            unsigned long long bp[4] = {B0.x, B0.y, B1.x, B1.y};
            #pragma unroll
            for (int r = 0; r < 8; r++)
                #pragma unroll
                for (int c = 0; c < 4; c++)
                    fma2(acc[r][c], ap[r], bp[c]);
        }

        if (more) {
            int nxt = cur ^ 1;
            *(float2*)&As2[nxt][a_col + 0][2 * a_row] = make_float2(av.x, av.x);
            *(float2*)&As2[nxt][a_col + 1][2 * a_row] = make_float2(av.y, av.y);
            *(float2*)&As2[nxt][a_col + 2][2 * a_row] = make_float2(av.z, av.z);
            *(float2*)&As2[nxt][a_col + 3][2 * a_row] = make_float2(av.w, av.w);
            *(float4*)&Bs[nxt][b_row][b_col] = bv;
            __syncthreads();
            cur = nxt;
        }
    }

    float4 bs0 = *(const float4*)&bias[bn + 4 * tx];
    float4 bs1 = *(const float4*)&bias[bn + 64 + 4 * tx];

    #pragma unroll
    for (int i = 0; i < 8; i++) {
        int row = bm + ((i < 4) ? (ty * 4 + i) : (64 + ty * 4 + (i - 4)));
        float2 p0 = up2(acc[i][0]);
        float2 p1 = up2(acc[i][1]);
        float2 p2 = up2(acc[i][2]);
        float2 p3 = up2(acc[i][3]);
        float* Cr = C + (size_t)row * N;
        *(float4*)&Cr[bn + 4 * tx] =
            make_float4(p0.x + bs0.x, p0.y + bs0.y, p1.x + bs0.z, p1.y + bs0.w);
        *(float4*)&Cr[bn + 64 + 4 * tx] =
            make_float4(p2.x + bs1.x, p2.y + bs1.y, p3.x + bs1.z, p3.y + bs1.w);
    }
}

// ---------------- persistent bidirectional LSTM scan (R12, unchanged) ----------------
__global__ void __launch_bounds__(256, 1)
lstm_scan(const float* __restrict__ xzf, const float* __restrict__ xzb,
          const float* __restrict__ Whf, const float* __restrict__ Whb,
          float* __restrict__ out, float* __restrict__ est_h, float* __restrict__ est_c) {
    extern __shared__ float sm[];
    float* w_s = sm;                     // 16384 floats
    float* h_s = sm + WS_F;              // 33792 floats
    float* z_s = sm + WS_F + HS_F;       // 2304 floats, stride 36 per row

    int tid = threadIdx.x;
    int dir = blockIdx.x >> 6;
    int u0  = (blockIdx.x & 63) * 8;
    unsigned* my_cnt = &g_cnt[blockIdx.x & 7];
    const float* xz = dir ? xzb : xzf;
    const float* Wh = dir ? Whb : Whf;

    for (int i = tid; i < WS_F; i += 256) {
        int kp = i >> 6, rem = i & 63;
        int c = rem >> 1, j = rem & 1;
        int ul = c >> 2, g = c & 3;
        w_s[i] = Wh[(size_t)(2 * kp + j) * GG + g * UU + u0 + ul];
    }
    __syncthreads();

    int tx = tid & 15, ty = tid >> 4;
    const float* hp = h_s + 8 * ty;
    const float* wq = w_s + 4 * tx;

    int erow = tid >> 3;
    int eul  = tid & 7;
    int eu   = u0 + eul;
    int ekp  = eu >> 1, elane = eu & 1;

    float cc0 = 0.f, cc1 = 0.f;

    for (int t = 0; t < TT; t++) {
        int ttv = dir ? (TT - 1 - t) : t;

        float z0a[4], z0b[4];
        #pragma unroll
        for (int g = 0; g < 4; g++) {
            z0a[g] = xz[(size_t)(erow * TT + ttv) * GG + g * UU + eu];
            z0b[g] = xz[(size_t)((erow + 32) * TT + ttv) * GG + g * UU + eu];
        }

        if (t > 0) {
            if (tid < 8) {
                const unsigned* f = &g_cnt[tid];
                unsigned target = 16u * (unsigned)t;
                unsigned v;
                do {
                    asm volatile("ld.acquire.gpu.u32 %0, [%1];" : "=r"(v) : "l"(f));
                } while (v < target);
            }
            __syncthreads();

            const float* hg = g_h2 + ((t & 1) * 2 + dir) * 32768;
            #pragma unroll 4
            for (int i = tid * 4; i < 32768; i += 1024) {
                float4 v = __ldcg((const float4*)(hg + i));
                *(float4*)&h_s[(i >> 7) * 132 + (i & 127)] = v;
            }
            __syncthreads();

            unsigned long long acc[4][2] = {{0,0},{0,0},{0,0},{0,0}};
            #pragma unroll 8
            for (int kp = 0; kp < 256; kp++) {
                ulonglong2 ha = *(const ulonglong2*)(hp + kp * 132);
                ulonglong2 hb = *(const ulonglong2*)(hp + kp * 132 + 4);
                ulonglong2 wv = *(const ulonglong2*)(wq + kp * 64);
                fma2(acc[0][0], ha.x, wv.x); fma2(acc[0][1], ha.x, wv.y);
                fma2(acc[1][0], ha.y, wv.x); fma2(acc[1][1], ha.y, wv.y);
                fma2(acc[2][0], hb.x, wv.x); fma2(acc[2][1], hb.x, wv.y);
                fma2(acc[3][0], hb.y, wv.x); fma2(acc[3][1], hb.y, wv.y);
            }

            #pragma unroll
            for (int r = 0; r < 4; r++) {
                float2 pa = up2(acc[r][0]);
                float2 pb = up2(acc[r][1]);
                *(float2*)&z_s[(4 * ty + r) * 36 + 2 * tx] =
                    make_float2(pa.x + pa.y, pb.x + pb.y);
            }
        }
        __syncthreads();

        float4 zr0 = make_float4(0.f, 0.f, 0.f, 0.f);
        float4 zr1 = make_float4(0.f, 0.f, 0.f, 0.f);
        if (t > 0) {
            zr0 = *(const float4*)&z_s[erow * 36 + eul * 4];
            zr1 = *(const float4*)&z_s[(erow + 32) * 36 + eul * 4];
        }

        float gi0 = sigf(z0a[0] + zr0.x), gf0 = sigf(z0a[1] + zr0.y);
        float gg0 = tanhf(z0a[2] + zr0.z), go0 = sigf(z0a[3] + zr0.w);
        cc0 = gf0 * cc0 + gi0 * gg0;
        float h0 = go0 * tanhf(cc0);

        float gi1 = sigf(z0b[0] + zr1.x), gf1 = sigf(z0b[1] + zr1.y);
        float gg1 = tanhf(z0b[2] + zr1.z), go1 = sigf(z0b[3] + zr1.w);
        cc1 = gf1 * cc1 + gi1 * gg1;
        float h1 = go1 * tanhf(cc1);

        bool not_last = (t + 1 < TT);
        if (not_last) {
            float* hn = g_h2 + (((t + 1) & 1) * 2 + dir) * 32768;
            hn[ekp * 128 + erow * 2 + elane]        = h0;
            hn[ekp * 128 + (erow + 32) * 2 + elane] = h1;
            __threadfence();
            __syncthreads();
            if (tid == 0) atomicAdd(my_cnt, 1u);
        }

        out[(size_t)(erow * TT + ttv) * 1024 + dir * UU + eu]        = h0;
        out[(size_t)((erow + 32) * TT + ttv) * 1024 + dir * UU + eu] = h1;

        if (est_h != nullptr && t == TT - 1) {
            est_h[erow * 1024 + dir * UU + eu]        = h0;
            est_h[(erow + 32) * 1024 + dir * UU + eu] = h1;
            est_c[erow * 1024 + dir * UU + eu]        = cc0;
            est_c[(erow + 32) * 1024 + dir * UU + eu] = cc1;
        }
    }
}

// ---------------- launch ----------------
extern "C" void kernel_launch(void* const* d_in, const int* in_sizes, int n_in,
                              void* d_out, int out_size) {
    const int*   tokens = (const int*)  d_in[0];
    const float* emb    = (const float*)d_in[1];
    const float* Wx_f0 = (const float*)d_in[2];
    const float* Wh_f0 = (const float*)d_in[3];
    const float* b_f0  = (const float*)d_in[4];
    const float* Wx_b0 = (const float*)d_in[5];
    const float* Wh_b0 = (const float*)d_in[6];
    const float* b_b0  = (const float*)d_in[7];
    const float* Wx_f1 = (const float*)d_in[8];
    const float* Wh_f1 = (const float*)d_in[9];
    const float* b_f1  = (const float*)d_in[10];
    const float* Wx_b1 = (const float*)d_in[11];
    const float* Wh_b1 = (const float*)d_in[12];
    const float* b_b1  = (const float*)d_in[13];
    float* out = (float*)d_out;

    float *x0p, *y0p, *xzfp, *xzbp;
    void* cntp;
    cudaGetSymbolAddress((void**)&x0p,  g_x0);
    cudaGetSymbolAddress((void**)&y0p,  g_y0);
    cudaGetSymbolAddress((void**)&xzfp, g_xzf);
    cudaGetSymbolAddress((void**)&xzbp, g_xzb);
    cudaGetSymbolAddress(&cntp, g_cnt);

    cudaFuncSetAttribute(lstm_scan, cudaFuncAttributeMaxDynamicSharedMemorySize, SCAN_SMEM);

    embed_kernel<<<(BT * 128 + 255) / 256, 256>>>(tokens, emb, x0p);

    dim3 g0(GG / 128, BT / 128);
    sgemm_bias<<<g0, 256>>>(x0p, Wx_f0, b_f0, xzfp, BT, GG, 512);
    sgemm_bias<<<g0, 256>>>(x0p, Wx_b0, b_b0, xzbp, BT, GG, 512);

    cudaMemsetAsync(cntp, 0, 8 * sizeof(unsigned));
    lstm_scan<<<NBLK, 256, SCAN_SMEM>>>(xzfp, xzbp, Wh_f0, Wh_b0, y0p,
                                        (float*)nullptr, (float*)nullptr);

    sgemm_bias<<<g0, 256>>>(y0p, Wx_f1, b_f1, xzfp, BT, GG, 1024);
    sgemm_bias<<<g0, 256>>>(y0p, Wx_b1, b_b1, xzbp, BT, GG, 1024);

    float* est_h = out + (size_t)BT * 1024;
    float* est_c = est_h + BB * 1024;
    cudaMemsetAsync(cntp, 0, 8 * sizeof(unsigned));
    lstm_scan<<<NBLK, 256, SCAN_SMEM>>>(xzfp, xzbp, Wh_f1, Wh_b1, out, est_h, est_c);
}

// round 14
// speedup vs baseline: 2.4441x; 1.0263x over previous
#include <cuda_runtime.h>
#include <cstdint>

#define BB 64
#define TT 256
#define UU 512
#define GG 2048
#define BT (BB*TT)

#define NBLK 128
// smem floats: w_s 16384 | h_s 256*132=33792
#define WS_F   16384
#define HS_F   33792
#define SCAN_SMEM ((WS_F + HS_F) * 4)   // 200704 B

// ---------------- static scratch ----------------
__device__ __align__(128) float g_x0 [BT * 512];
__device__ __align__(128) float g_y0 [BT * 1024];
__device__ __align__(128) float g_xzf[BT * GG];
__device__ __align__(128) float g_xzb[BT * GG];
// h exchange, k-pair packed + transposed: [buf][dir][kp][row][lane]
__device__ __align__(128) float g_h2 [2 * 2 * 32768];
// per-direction distributed monotonic arrival counters: [dir][8], 128B apart
__device__ __align__(128) unsigned g_cnt[2 * 32];

// ---------------- packed fp32 helpers ----------------
__device__ __forceinline__ void fma2(unsigned long long& d, unsigned long long a,
                                     unsigned long long b) {
    asm("fma.rn.f32x2 %0, %1, %2, %0;" : "+l"(d) : "l"(a), "l"(b));
}
__device__ __forceinline__ float2 up2(unsigned long long u) {
    float2 f; asm("mov.b64 {%0,%1}, %2;" : "=f"(f.x), "=f"(f.y) : "l"(u)); return f;
}
__device__ __forceinline__ float sigf(float x) { return 1.0f / (1.0f + expf(-x)); }

// ---------------- embedding gather ----------------
__global__ void embed_kernel(const int* __restrict__ tokens,
                             const float* __restrict__ emb,
                             float* __restrict__ x0) {
    int i = blockIdx.x * 256 + threadIdx.x;
    if (i >= BT * 128) return;
    int row = i >> 7;
    int c4  = (i & 127) << 2;
    int tok = tokens[row];
    *(float4*)&x0[row * 512 + c4] = *(const float4*)&emb[tok * 512 + c4];
}

// ---------------- SGEMM: C = A(MxK) @ W(KxN) + bias (R13, unchanged) ----------------
__global__ void __launch_bounds__(256, 2)
sgemm_bias(const float* __restrict__ A, const float* __restrict__ W,
           const float* __restrict__ bias, float* __restrict__ C,
           int M, int N, int K) {
    __shared__ float As2[2][8][256];   // [buf][k][2*row+lane] (dup)
    __shared__ float Bs [2][8][128];   // [buf][k][col]

    int tid = threadIdx.x;
    int bm = blockIdx.y * 128;
    int bn = blockIdx.x * 128;
    int tx = tid & 15, ty = tid >> 4;

    int a_row = tid >> 1;
    int a_col = (tid & 1) * 4;
    int b_row = tid >> 5;
    int b_col = (tid & 31) * 4;

    unsigned long long acc[8][4];
    #pragma unroll
    for (int i = 0; i < 8; i++)
        #pragma unroll
        for (int j = 0; j < 4; j++) acc[i][j] = 0ull;

    const float* Ap = A + (size_t)(bm + a_row) * K + a_col;
    const float* Wp = W + (size_t)b_row * N + bn + b_col;

    {
        float4 av = *(const float4*)(Ap);
        float4 bv = *(const float4*)(Wp);
        *(float2*)&As2[0][a_col + 0][2 * a_row] = make_float2(av.x, av.x);
        *(float2*)&As2[0][a_col + 1][2 * a_row] = make_float2(av.y, av.y);
        *(float2*)&As2[0][a_col + 2][2 * a_row] = make_float2(av.z, av.z);
        *(float2*)&As2[0][a_col + 3][2 * a_row] = make_float2(av.w, av.w);
        *(float4*)&Bs[0][b_row][b_col] = bv;
    }
    __syncthreads();

    int cur = 0;
    for (int k0 = 8; k0 <= K; k0 += 8) {
        float4 av, bv;
        bool more = (k0 < K);
        if (more) {
            av = *(const float4*)(Ap + k0);
            bv = *(const float4*)(Wp + (size_t)k0 * N);
        }

        #pragma unroll
        for (int k = 0; k < 8; k++) {
            ulonglong2 A0 = *(const ulonglong2*)&As2[cur][k][2 * (ty * 4)];
            ulonglong2 A1 = *(const ulonglong2*)&As2[cur][k][2 * (ty * 4 + 2)];
            ulonglong2 A2 = *(const ulonglong2*)&As2[cur][k][2 * (64 + ty * 4)];
            ulonglong2 A3 = *(const ulonglong2*)&As2[cur][k][2 * (64 + ty * 4 + 2)];
            ulonglong2 B0 = *(const ulonglong2*)&Bs[cur][k][4 * tx];
            ulonglong2 B1 = *(const ulonglong2*)&Bs[cur][k][64 + 4 * tx];
            unsigned long long ap[8] = {A0.x, A0.y, A1.x, A1.y, A2.x, A2.y, A3.x, A3.y};
            unsigned long long bp[4] = {B0.x, B0.y, B1.x, B1.y};
            #pragma unroll
            for (int r = 0; r < 8; r++)
                #pragma unroll
                for (int c = 0; c < 4; c++)
                    fma2(acc[r][c], ap[r], bp[c]);
        }

        if (more) {
            int nxt = cur ^ 1;
            *(float2*)&As2[nxt][a_col + 0][2 * a_row] = make_float2(av.x, av.x);
            *(float2*)&As2[nxt][a_col + 1][2 * a_row] = make_float2(av.y, av.y);
            *(float2*)&As2[nxt][a_col + 2][2 * a_row] = make_float2(av.z, av.z);
            *(float2*)&As2[nxt][a_col + 3][2 * a_row] = make_float2(av.w, av.w);
            *(float4*)&Bs[nxt][b_row][b_col] = bv;
            __syncthreads();
            cur = nxt;
        }
    }

    float4 bs0 = *(const float4*)&bias[bn + 4 * tx];
    float4 bs1 = *(const float4*)&bias[bn + 64 + 4 * tx];

    #pragma unroll
    for (int i = 0; i < 8; i++) {
        int row = bm + ((i < 4) ? (ty * 4 + i) : (64 + ty * 4 + (i - 4)));
        float2 p0 = up2(acc[i][0]);
        float2 p1 = up2(acc[i][1]);
        float2 p2 = up2(acc[i][2]);
        float2 p3 = up2(acc[i][3]);
        float* Cr = C + (size_t)row * N;
        *(float4*)&Cr[bn + 4 * tx] =
            make_float4(p0.x + bs0.x, p0.y + bs0.y, p1.x + bs0.z, p1.y + bs0.w);
        *(float4*)&Cr[bn + 64 + 4 * tx] =
            make_float4(p2.x + bs1.x, p2.y + bs1.y, p3.x + bs1.z, p3.y + bs1.w);
    }
}

// ---------------- persistent bidirectional LSTM scan ----------------
// 128 blocks x 256 threads. dir = blockIdx>>6, unit slice u0 = (blockIdx&63)*8.
// GEMM: thread (tx,ty) computes rows 4ty..4ty+3 x gate-cols 2tx,2tx+1 (k-pair lanes).
// Epilogue: thread PAIR (tx, tx^1) owns unit u0+(tx>>1); even lane holds (i,f),
//   odd (g,o); 4 xor-1 shuffles swap half the rows so each thread gets all 4 gates
//   for its 2 rows: row0 = 4ty + 2(tx&1). c-state in registers (stable ownership).
// Sync: per-direction split barrier. Arrive: syncthreads; tid0 red.release.gpu.
//   Wait (tid<8): acquire-poll g_cnt[dir*32+tid] >= 8*t.
__global__ void __launch_bounds__(256, 1)
lstm_scan(const float* __restrict__ xzf, const float* __restrict__ xzb,
          const float* __restrict__ Whf, const float* __restrict__ Whb,
          float* __restrict__ out, float* __restrict__ est_h, float* __restrict__ est_c) {
    extern __shared__ float sm[];
    float* w_s = sm;                     // 16384 floats
    float* h_s = sm + WS_F;              // 33792 floats (kp stride 132)

    int tid = threadIdx.x;
    int dir = blockIdx.x >> 6;
    int blk = blockIdx.x & 63;
    int u0  = blk * 8;
    unsigned* my_cnt = &g_cnt[dir * 32 + (blk & 7)];
    const float* xz = dir ? xzb : xzf;
    const float* Wh = dir ? Whb : Whf;

    // stage Wh slice (once): w_s[kp*64 + c*2 + j] = Wh[2kp+j][g*512 + u0 + ul], c=ul*4+g
    for (int i = tid; i < WS_F; i += 256) {
        int kp = i >> 6, rem = i & 63;
        int c = rem >> 1, j = rem & 1;
        int ul = c >> 2, g = c & 3;
        w_s[i] = Wh[(size_t)(2 * kp + j) * GG + g * UU + u0 + ul];
    }
    __syncthreads();

    int tx = tid & 15, ty = tid >> 4;
    const float* hp = h_s + 8 * ty;      // + kp*132
    const float* wq = w_s + 4 * tx;      // + kp*64

    bool evenx = (tx & 1) == 0;
    int row0 = 4 * ty + 2 * (tx & 1);    // this thread's epilogue rows: row0, row0+1
    int row1 = row0 + 1;
    int eu   = u0 + (tx >> 1);           // this thread's unit
    int ekp  = eu >> 1, elane = eu & 1;

    float cc0 = 0.f, cc1 = 0.f;

    for (int t = 0; t < TT; t++) {
        int ttv = dir ? (TT - 1 - t) : t;

        // prefetch input projections for this thread's cells (in flight across wait)
        float za[4], zb[4];
        #pragma unroll
        for (int g = 0; g < 4; g++) {
            za[g] = xz[(size_t)(row0 * TT + ttv) * GG + g * UU + eu];
            zb[g] = xz[(size_t)(row1 * TT + ttv) * GG + g * UU + eu];
        }

        float s0[4] = {0.f, 0.f, 0.f, 0.f};   // col 2tx sums, rows 4ty..4ty+3
        float s1[4] = {0.f, 0.f, 0.f, 0.f};   // col 2tx+1 sums

        if (t > 0) {
            // wait: all 64 blocks of THIS direction arrived for step t-1
            if (tid < 8) {
                const unsigned* f = &g_cnt[dir * 32 + tid];
                unsigned target = 8u * (unsigned)t;
                unsigned v;
                do {
                    asm volatile("ld.acquire.gpu.u32 %0, [%1];" : "=r"(v) : "l"(f));
                } while (v < target);
            }
            __syncthreads();

            // stage full h (32768 floats): coalesced copy with stride pad
            const float* hg = g_h2 + ((t & 1) * 2 + dir) * 32768;
            #pragma unroll 4
            for (int i = tid * 4; i < 32768; i += 1024) {
                float4 v = __ldcg((const float4*)(hg + i));
                *(float4*)&h_s[(i >> 7) * 132 + (i & 127)] = v;
            }
            __syncthreads();

            unsigned long long acc[4][2] = {{0,0},{0,0},{0,0},{0,0}};
            #pragma unroll 8
            for (int kp = 0; kp < 256; kp++) {
                ulonglong2 ha = *(const ulonglong2*)(hp + kp * 132);
                ulonglong2 hb = *(const ulonglong2*)(hp + kp * 132 + 4);
                ulonglong2 wv = *(const ulonglong2*)(wq + kp * 64);
                fma2(acc[0][0], ha.x, wv.x); fma2(acc[0][1], ha.x, wv.y);
                fma2(acc[1][0], ha.y, wv.x); fma2(acc[1][1], ha.y, wv.y);
                fma2(acc[2][0], hb.x, wv.x); fma2(acc[2][1], hb.x, wv.y);
                fma2(acc[3][0], hb.y, wv.x); fma2(acc[3][1], hb.y, wv.y);
            }

            #pragma unroll
            for (int r = 0; r < 4; r++) {
                float2 pa = up2(acc[r][0]);
                float2 pb = up2(acc[r][1]);
                s0[r] = pa.x + pa.y;
                s1[r] = pb.x + pb.y;
            }
        }

        // butterfly exchange with partner (tx^1): even sends rows 2,3; odd sends rows 0,1
        float e0 = __shfl_xor_sync(0xffffffffu, evenx ? s0[2] : s0[0], 1);
        float e1 = __shfl_xor_sync(0xffffffffu, evenx ? s1[2] : s1[0], 1);
        float e2 = __shfl_xor_sync(0xffffffffu, evenx ? s0[3] : s0[1], 1);
        float e3 = __shfl_xor_sync(0xffffffffu, evenx ? s1[3] : s1[1], 1);

        // gate pre-activations for this thread's 2 rows
        float zi0 = evenx ? s0[0] : e0;   float zf0 = evenx ? s1[0] : e1;
        float zg0 = evenx ? e0    : s0[2]; float zo0 = evenx ? e1    : s1[2];
        float zi1 = evenx ? s0[1] : e2;   float zf1 = evenx ? s1[1] : e3;
        float zg1 = evenx ? e2    : s0[3]; float zo1 = evenx ? e3    : s1[3];

        float gi0 = sigf(za[0] + zi0), gf0 = sigf(za[1] + zf0);
        float gg0 = tanhf(za[2] + zg0), go0 = sigf(za[3] + zo0);
        cc0 = gf0 * cc0 + gi0 * gg0;
        float h0 = go0 * tanhf(cc0);

        float gi1 = sigf(zb[0] + zi1), gf1 = sigf(zb[1] + zf1);
        float gg1 = tanhf(zb[2] + zg1), go1 = sigf(zb[3] + zo1);
        cc1 = gf1 * cc1 + gi1 * gg1;
        float h1 = go1 * tanhf(cc1);

        bool not_last = (t + 1 < TT);
        if (not_last) {
            float* hn = g_h2 + (((t + 1) & 1) * 2 + dir) * 32768;
            hn[ekp * 128 + row0 * 2 + elane] = h0;
            hn[ekp * 128 + row1 * 2 + elane] = h1;
            __syncthreads();                 // all h stores of this block done
            if (tid == 0)
                asm volatile("red.release.gpu.global.add.u32 [%0], %1;"
                             :: "l"(my_cnt), "r"(1u) : "memory");
        }

        // overlap other blocks' arrivals (wait happens next iteration)
        out[(size_t)(row0 * TT + ttv) * 1024 + dir * UU + eu] = h0;
        out[(size_t)(row1 * TT + ttv) * 1024 + dir * UU + eu] = h1;

        if (est_h != nullptr && t == TT - 1) {
            est_h[row0 * 1024 + dir * UU + eu] = h0;
            est_h[row1 * 1024 + dir * UU + eu] = h1;
            est_c[row0 * 1024 + dir * UU + eu] = cc0;
            est_c[row1 * 1024 + dir * UU + eu] = cc1;
        }
    }
}

// ---------------- launch ----------------
extern "C" void kernel_launch(void* const* d_in, const int* in_sizes, int n_in,
                              void* d_out, int out_size) {
    const int*   tokens = (const int*)  d_in[0];
    const float* emb    = (const float*)d_in[1];
    const float* Wx_f0 = (const float*)d_in[2];
    const float* Wh_f0 = (const float*)d_in[3];
    const float* b_f0  = (const float*)d_in[4];
    const float* Wx_b0 = (const float*)d_in[5];
    const float* Wh_b0 = (const float*)d_in[6];
    const float* b_b0  = (const float*)d_in[7];
    const float* Wx_f1 = (const float*)d_in[8];
    const float* Wh_f1 = (const float*)d_in[9];
    const float* b_f1  = (const float*)d_in[10];
    const float* Wx_b1 = (const float*)d_in[11];
    const float* Wh_b1 = (const float*)d_in[12];
    const float* b_b1  = (const float*)d_in[13];
    float* out = (float*)d_out;

    float *x0p, *y0p, *xzfp, *xzbp;
    void* cntp;
    cudaGetSymbolAddress((void**)&x0p,  g_x0);
    cudaGetSymbolAddress((void**)&y0p,  g_y0);
    cudaGetSymbolAddress((void**)&xzfp, g_xzf);
    cudaGetSymbolAddress((void**)&xzbp, g_xzb);
    cudaGetSymbolAddress(&cntp, g_cnt);

    cudaFuncSetAttribute(lstm_scan, cudaFuncAttributeMaxDynamicSharedMemorySize, SCAN_SMEM);

    embed_kernel<<<(BT * 128 + 255) / 256, 256>>>(tokens, emb, x0p);

    dim3 g0(GG / 128, BT / 128);
    sgemm_bias<<<g0, 256>>>(x0p, Wx_f0, b_f0, xzfp, BT, GG, 512);
    sgemm_bias<<<g0, 256>>>(x0p, Wx_b0, b_b0, xzbp, BT, GG, 512);

    cudaMemsetAsync(cntp, 0, 2 * 32 * sizeof(unsigned));
    lstm_scan<<<NBLK, 256, SCAN_SMEM>>>(xzfp, xzbp, Wh_f0, Wh_b0, y0p,
                                        (float*)nullptr, (float*)nullptr);

    sgemm_bias<<<g0, 256>>>(y0p, Wx_f1, b_f1, xzfp, BT, GG, 1024);
    sgemm_bias<<<g0, 256>>>(y0p, Wx_b1, b_b1, xzbp, BT, GG, 1024);

    float* est_h = out + (size_t)BT * 1024;
    float* est_c = est_h + BB * 1024;
    cudaMemsetAsync(cntp, 0, 2 * 32 * sizeof(unsigned));
    lstm_scan<<<NBLK, 256, SCAN_SMEM>>>(xzfp, xzbp, Wh_f1, Wh_b1, out, est_h, est_c);
}

// round 15
// speedup vs baseline: 2.7343x; 1.1188x over previous
#include <cuda_runtime.h>
#include <cstdint>

#define BB 64
#define TT 256
#define UU 512
#define GG 2048
#define BT (BB*TT)

#define NBLK 128
// smem floats: w_s 256*68=17408 | h_s 256*132=33792 | red_s 2048
#define WS_F   17408
#define HS_F   33792
#define RS_F   2048
#define SCAN_SMEM ((WS_F + HS_F + RS_F) * 4)   // 212992 B

// ---------------- static scratch ----------------
__device__ __align__(128) float g_x0 [BT * 512];
__device__ __align__(128) float g_y0 [BT * 1024];
__device__ __align__(128) float g_xzf[BT * GG];
__device__ __align__(128) float g_xzb[BT * GG];
// h exchange, k-pair packed + transposed: [buf][dir][kp][row][lane]
__device__ __align__(128) float g_h2 [2 * 2 * 32768];
// per-direction distributed monotonic arrival counters: [dir][8], 128B apart
__device__ __align__(128) unsigned g_cnt[2 * 32];

// ---------------- packed fp32 helpers ----------------
__device__ __forceinline__ void fma2(unsigned long long& d, unsigned long long a,
                                     unsigned long long b) {
    asm("fma.rn.f32x2 %0, %1, %2, %0;" : "+l"(d) : "l"(a), "l"(b));
}
__device__ __forceinline__ float2 up2(unsigned long long u) {
    float2 f; asm("mov.b64 {%0,%1}, %2;" : "=f"(f.x), "=f"(f.y) : "l"(u)); return f;
}
__device__ __forceinline__ float sigf(float x) { return 1.0f / (1.0f + expf(-x)); }

// ---------------- embedding gather ----------------
__global__ void embed_kernel(const int* __restrict__ tokens,
                             const float* __restrict__ emb,
                             float* __restrict__ x0) {
    int i = blockIdx.x * 256 + threadIdx.x;
    if (i >= BT * 128) return;
    int row = i >> 7;
    int c4  = (i & 127) << 2;
    int tok = tokens[row];
    *(float4*)&x0[row * 512 + c4] = *(const float4*)&emb[tok * 512 + c4];
}

// ---------------- SGEMM: C = A(MxK) @ W(KxN) + bias (R13, unchanged) ----------------
__global__ void __launch_bounds__(256, 2)
sgemm_bias(const float* __restrict__ A, const float* __restrict__ W,
           const float* __restrict__ bias, float* __restrict__ C,
           int M, int N, int K) {
    __shared__ float As2[2][8][256];   // [buf][k][2*row+lane] (dup)
    __shared__ float Bs [2][8][128];   // [buf][k][col]

    int tid = threadIdx.x;
    int bm = blockIdx.y * 128;
    int bn = blockIdx.x * 128;
    int tx = tid & 15, ty = tid >> 4;

    int a_row = tid >> 1;
    int a_col = (tid & 1) * 4;
    int b_row = tid >> 5;
    int b_col = (tid & 31) * 4;

    unsigned long long acc[8][4];
    #pragma unroll
    for (int i = 0; i < 8; i++)
        #pragma unroll
        for (int j = 0; j < 4; j++) acc[i][j] = 0ull;

    const float* Ap = A + (size_t)(bm + a_row) * K + a_col;
    const float* Wp = W + (size_t)b_row * N + bn + b_col;

    {
        float4 av = *(const float4*)(Ap);
        float4 bv = *(const float4*)(Wp);
        *(float2*)&As2[0][a_col + 0][2 * a_row] = make_float2(av.x, av.x);
        *(float2*)&As2[0][a_col + 1][2 * a_row] = make_float2(av.y, av.y);
        *(float2*)&As2[0][a_col + 2][2 * a_row] = make_float2(av.z, av.z);
        *(float2*)&As2[0][a_col + 3][2 * a_row] = make_float2(av.w, av.w);
        *(float4*)&Bs[0][b_row][b_col] = bv;
    }
    __syncthreads();

    int cur = 0;
    for (int k0 = 8; k0 <= K; k0 += 8) {
        float4 av, bv;
        bool more = (k0 < K);
        if (more) {
            av = *(const float4*)(Ap + k0);
            bv = *(const float4*)(Wp + (size_t)k0 * N);
        }

        #pragma unroll
        for (int k = 0; k < 8; k++) {
            ulonglong2 A0 = *(const ulonglong2*)&As2[cur][k][2 * (ty * 4)];
            ulonglong2 A1 = *(const ulonglong2*)&As2[cur][k][2 * (ty * 4 + 2)];
            ulonglong2 A2 = *(const ulonglong2*)&As2[cur][k][2 * (64 + ty * 4)];
            ulonglong2 A3 = *(const ulonglong2*)&As2[cur][k][2 * (64 + ty * 4 + 2)];
            ulonglong2 B0 = *(const ulonglong2*)&Bs[cur][k][4 * tx];
            ulonglong2 B1 = *(const ulonglong2*)&Bs[cur][k][64 + 4 * tx];
            unsigned long long ap[8] = {A0.x, A0.y, A1.x, A1.y, A2.x, A2.y, A3.x, A3.y};
            unsigned long long bp[4] = {B0.x, B0.y, B1.x, B1.y};
            #pragma unroll
            for (int r = 0; r < 8; r++)
                #pragma unroll
                for (int c = 0; c < 4; c++)
                    fma2(acc[r][c], ap[r], bp[c]);
        }

        if (more) {
            int nxt = cur ^ 1;
            *(float2*)&As2[nxt][a_col + 0][2 * a_row] = make_float2(av.x, av.x);
            *(float2*)&As2[nxt][a_col + 1][2 * a_row] = make_float2(av.y, av.y);
            *(float2*)&As2[nxt][a_col + 2][2 * a_row] = make_float2(av.z, av.z);
            *(float2*)&As2[nxt][a_col + 3][2 * a_row] = make_float2(av.w, av.w);
            *(float4*)&Bs[nxt][b_row][b_col] = bv;
            __syncthreads();
            cur = nxt;
        }
    }

    float4 bs0 = *(const float4*)&bias[bn + 4 * tx];
    float4 bs1 = *(const float4*)&bias[bn + 64 + 4 * tx];

    #pragma unroll
    for (int i = 0; i < 8; i++) {
        int row = bm + ((i < 4) ? (ty * 4 + i) : (64 + ty * 4 + (i - 4)));
        float2 p0 = up2(acc[i][0]);
        float2 p1 = up2(acc[i][1]);
        float2 p2 = up2(acc[i][2]);
        float2 p3 = up2(acc[i][3]);
        float* Cr = C + (size_t)row * N;
        *(float4*)&Cr[bn + 4 * tx] =
            make_float4(p0.x + bs0.x, p0.y + bs0.y, p1.x + bs0.z, p1.y + bs0.w);
        *(float4*)&Cr[bn + 64 + 4 * tx] =
            make_float4(p2.x + bs1.x, p2.y + bs1.y, p3.x + bs1.z, p3.y + bs1.w);
    }
}

// ---------------- persistent bidirectional LSTM scan (4r x 4c split-k) ----------------
// 128 blocks x 256 threads. dir = blockIdx>>6, u0 = (blockIdx&63)*8.
// Thread: kh = tid>>7 (k parity), q = tid&127, tx = q&7 (unit), ty = q>>3 (4 rows).
// GEMM: thread computes rows 4ty..4ty+3 x unit u0+tx's 4 gates over kp of parity kh.
// w_s [kp][68], unit block at 8*ul + 4*(ul>>2) (bank-staggered), inner (g,j) = 2g+j.
// h_s [kp][132]: h_s[kp*132 + 2*row + lane] = h[2kp+lane][row].
// Staging: 4 chunks x 64 kp, chunk c+1 LDGs issued before chunk-c FMAs (overlap).
// Reduction: kh=1 stores 16 partials to red_s; kh=0 adds. Epilogue/c-state: kh=0 only.
// Sync: per-direction split barrier (R14, unchanged).
__global__ void __launch_bounds__(256, 1)
lstm_scan(const float* __restrict__ xzf, const float* __restrict__ xzb,
          const float* __restrict__ Whf, const float* __restrict__ Whb,
          float* __restrict__ out, float* __restrict__ est_h, float* __restrict__ est_c) {
    extern __shared__ float sm[];
    float* w_s   = sm;                       // 17408 floats
    float* h_s   = sm + WS_F;                // 33792 floats (kp stride 132)
    float* red_s = sm + WS_F + HS_F;         // 2048 floats

    int tid = threadIdx.x;
    int dir = blockIdx.x >> 6;
    int blk = blockIdx.x & 63;
    int u0  = blk * 8;
    unsigned* my_cnt = &g_cnt[dir * 32 + (blk & 7)];
    const float* xz = dir ? xzb : xzf;
    const float* Wh = dir ? Whb : Whf;

    // stage Wh slice (once), bank-staggered layout
    for (int i = tid; i < 256 * 64; i += 256) {
        int kp = i >> 6, rem = i & 63;
        int ul = rem >> 3, w8 = rem & 7;
        int g = w8 >> 1, j = w8 & 1;
        w_s[kp * 68 + 8 * ul + 4 * (ul >> 2) + w8] =
            Wh[(size_t)(2 * kp + j) * GG + g * UU + u0 + ul];
    }
    __syncthreads();

    int kh = tid >> 7;
    int q  = tid & 127;
    int tx = q & 7;
    int ty = q >> 3;                       // 0..15
    const float* hp = h_s + 8 * ty;        // + kp*132
    const float* wq = w_s + 8 * tx + 4 * (tx >> 2);   // + kp*68

    int eu  = u0 + tx;
    int ekp = eu >> 1, elane = eu & 1;

    float cc[4] = {0.f, 0.f, 0.f, 0.f};

    for (int t = 0; t < TT; t++) {
        int ttv = dir ? (TT - 1 - t) : t;

        // prefetch input projections (kh=0 cells only; in flight across the wait)
        float za[4][4];
        if (kh == 0) {
            #pragma unroll
            for (int r = 0; r < 4; r++)
                #pragma unroll
                for (int g = 0; g < 4; g++)
                    za[r][g] = xz[(size_t)((4 * ty + r) * TT + ttv) * GG + g * UU + eu];
        }

        float s[4][4];
        #pragma unroll
        for (int r = 0; r < 4; r++)
            #pragma unroll
            for (int c = 0; c < 4; c++) s[r][c] = 0.f;

        if (t > 0) {
            // wait: all 64 blocks of THIS direction arrived for step t-1
            if (tid < 8) {
                const unsigned* f = &g_cnt[dir * 32 + tid];
                unsigned target = 8u * (unsigned)t;
                unsigned v;
                do {
                    asm volatile("ld.acquire.gpu.u32 %0, [%1];" : "=r"(v) : "l"(f));
                } while (v < target);
            }
            __syncthreads();

            const float* hg = g_h2 + ((t & 1) * 2 + dir) * 32768;

            // stage chunk 0 (kp 0..63 = floats 0..8191)
            #pragma unroll
            for (int j = 0; j < 8; j++) {
                int i = tid * 4 + j * 1024;
                float4 v = __ldcg((const float4*)(hg + i));
                *(float4*)&h_s[(i >> 7) * 132 + (i & 127)] = v;
            }
            __syncthreads();

            unsigned long long acc[4][4];
            #pragma unroll
            for (int r = 0; r < 4; r++)
                #pragma unroll
                for (int c = 0; c < 4; c++) acc[r][c] = 0ull;

            #pragma unroll
            for (int ch = 0; ch < 4; ch++) {
                float4 pre[8];
                if (ch < 3) {
                    #pragma unroll
                    for (int j = 0; j < 8; j++)
                        pre[j] = __ldcg((const float4*)(hg + 8192 * (ch + 1) + tid * 4 + j * 1024));
                }

                // GEMM on chunk ch: kp = 64*ch + 2*i2 + kh
                const float* hpc = hp + (size_t)(64 * ch + kh) * 132;
                const float* wqc = wq + (size_t)(64 * ch + kh) * 68;
                #pragma unroll 8
                for (int i2 = 0; i2 < 32; i2++) {
                    ulonglong2 ha = *(const ulonglong2*)(hpc + i2 * 264);
                    ulonglong2 hb = *(const ulonglong2*)(hpc + i2 * 264 + 4);
                    ulonglong2 wa = *(const ulonglong2*)(wqc + i2 * 136);
                    ulonglong2 wb = *(const ulonglong2*)(wqc + i2 * 136 + 4);
                    fma2(acc[0][0], ha.x, wa.x); fma2(acc[0][1], ha.x, wa.y);
                    fma2(acc[0][2], ha.x, wb.x); fma2(acc[0][3], ha.x, wb.y);
                    fma2(acc[1][0], ha.y, wa.x); fma2(acc[1][1], ha.y, wa.y);
                    fma2(acc[1][2], ha.y, wb.x); fma2(acc[1][3], ha.y, wb.y);
                    fma2(acc[2][0], hb.x, wa.x); fma2(acc[2][1], hb.x, wa.y);
                    fma2(acc[2][2], hb.x, wb.x); fma2(acc[2][3], hb.x, wb.y);
                    fma2(acc[3][0], hb.y, wa.x); fma2(acc[3][1], hb.y, wa.y);
                    fma2(acc[3][2], hb.y, wb.x); fma2(acc[3][3], hb.y, wb.y);
                }

                if (ch < 3) {
                    #pragma unroll
                    for (int j = 0; j < 8; j++) {
                        int i = 8192 * (ch + 1) + tid * 4 + j * 1024;
                        *(float4*)&h_s[(i >> 7) * 132 + (i & 127)] = pre[j];
                    }
                    __syncthreads();
                }
            }

            // collapse f32x2 lanes
            #pragma unroll
            for (int r = 0; r < 4; r++)
                #pragma unroll
                for (int c = 0; c < 4; c++) {
                    float2 p = up2(acc[r][c]);
                    s[r][c] = p.x + p.y;
                }

            // cross-half reduction: kh=1 stores, kh=0 adds
            if (kh == 1) {
                #pragma unroll
                for (int r = 0; r < 4; r++)
                    *(float4*)&red_s[r * 512 + q * 4] =
                        make_float4(s[r][0], s[r][1], s[r][2], s[r][3]);
            }
            __syncthreads();
            if (kh == 0) {
                #pragma unroll
                for (int r = 0; r < 4; r++) {
                    float4 v = *(const float4*)&red_s[r * 512 + q * 4];
                    s[r][0] += v.x; s[r][1] += v.y; s[r][2] += v.z; s[r][3] += v.w;
                }
            }
        }

        float h4[4];
        if (kh == 0) {
            #pragma unroll
            for (int r = 0; r < 4; r++) {
                float gi = sigf(za[r][0] + s[r][0]);
                float gf = sigf(za[r][1] + s[r][1]);
                float gg = tanhf(za[r][2] + s[r][2]);
                float go = sigf(za[r][3] + s[r][3]);
                cc[r] = gf * cc[r] + gi * gg;
                h4[r] = go * tanhf(cc[r]);
            }
        }

        bool not_last = (t + 1 < TT);
        if (not_last) {
            if (kh == 0) {
                float* hn = g_h2 + (((t + 1) & 1) * 2 + dir) * 32768;
                #pragma unroll
                for (int r = 0; r < 4; r++)
                    hn[ekp * 128 + 2 * (4 * ty + r) + elane] = h4[r];
            }
            __syncthreads();                 // all h stores of this block done
            if (tid == 0)
                asm volatile("red.release.gpu.global.add.u32 [%0], %1;"
                             :: "l"(my_cnt), "r"(1u) : "memory");
        }

        // overlap other blocks' arrivals (wait happens next iteration)
        if (kh == 0) {
            #pragma unroll
            for (int r = 0; r < 4; r++)
                out[(size_t)((4 * ty + r) * TT + ttv) * 1024 + dir * UU + eu] = h4[r];

            if (est_h != nullptr && t == TT - 1) {
                #pragma unroll
                for (int r = 0; r < 4; r++) {
                    est_h[(4 * ty + r) * 1024 + dir * UU + eu] = h4[r];
                    est_c[(4 * ty + r) * 1024 + dir * UU + eu] = cc[r];
                }
            }
        }
    }
}

// ---------------- launch ----------------
extern "C" void kernel_launch(void* const* d_in, const int* in_sizes, int n_in,
                              void* d_out, int out_size) {
    const int*   tokens = (const int*)  d_in[0];
    const float* emb    = (const float*)d_in[1];
    const float* Wx_f0 = (const float*)d_in[2];
    const float* Wh_f0 = (const float*)d_in[3];
    const float* b_f0  = (const float*)d_in[4];
    const float* Wx_b0 = (const float*)d_in[5];
    const float* Wh_b0 = (const float*)d_in[6];
    const float* b_b0  = (const float*)d_in[7];
    const float* Wx_f1 = (const float*)d_in[8];
    const float* Wh_f1 = (const float*)d_in[9];
    const float* b_f1  = (const float*)d_in[10];
    const float* Wx_b1 = (const float*)d_in[11];
    const float* Wh_b1 = (const float*)d_in[12];
    const float* b_b1  = (const float*)d_in[13];
    float* out = (float*)d_out;

    float *x0p, *y0p, *xzfp, *xzbp;
    void* cntp;
    cudaGetSymbolAddress((void**)&x0p,  g_x0);
    cudaGetSymbolAddress((void**)&y0p,  g_y0);
    cudaGetSymbolAddress((void**)&xzfp, g_xzf);
    cudaGetSymbolAddress((void**)&xzbp, g_xzb);
    cudaGetSymbolAddress(&cntp, g_cnt);

    cudaFuncSetAttribute(lstm_scan, cudaFuncAttributeMaxDynamicSharedMemorySize, SCAN_SMEM);

    embed_kernel<<<(BT * 128 + 255) / 256, 256>>>(tokens, emb, x0p);

    dim3 g0(GG / 128, BT / 128);
    sgemm_bias<<<g0, 256>>>(x0p, Wx_f0, b_f0, xzfp, BT, GG, 512);
    sgemm_bias<<<g0, 256>>>(x0p, Wx_b0, b_b0, xzbp, BT, GG, 512);

    cudaMemsetAsync(cntp, 0, 2 * 32 * sizeof(unsigned));
    lstm_scan<<<NBLK, 256, SCAN_SMEM>>>(xzfp, xzbp, Wh_f0, Wh_b0, y0p,
                                        (float*)nullptr, (float*)nullptr);

    sgemm_bias<<<g0, 256>>>(y0p, Wx_f1, b_f1, xzfp, BT, GG, 1024);
    sgemm_bias<<<g0, 256>>>(y0p, Wx_b1, b_b1, xzbp, BT, GG, 1024);

    float* est_h = out + (size_t)BT * 1024;
    float* est_c = est_h + BB * 1024;
    cudaMemsetAsync(cntp, 0, 2 * 32 * sizeof(unsigned));
    lstm_scan<<<NBLK, 256, SCAN_SMEM>>>(xzfp, xzbp, Wh_f1, Wh_b1, out, est_h, est_c);
}

// round 16
// speedup vs baseline: 2.7407x; 1.0023x over previous
#include <cuda_runtime.h>
#include <cstdint>

#define BB 64
#define TT 256
#define UU 512
#define GG 2048
#define BT (BB*TT)

#define NBLK 128
// smem floats: w_s 256*68=17408 | h_s 256*132=33792 | red_s 2048
#define WS_F   17408
#define HS_F   33792
#define RS_F   2048
#define SCAN_SMEM ((WS_F + HS_F + RS_F) * 4)   // 212992 B

// ---------------- static scratch ----------------
__device__ __align__(128) float g_x0 [BT * 512];
__device__ __align__(128) float g_y0 [BT * 1024];
__device__ __align__(128) float g_xzf[BT * GG];
__device__ __align__(128) float g_xzb[BT * GG];
// h exchange, k-pair packed + transposed: [buf][dir][kp][row][lane]
__device__ __align__(128) float g_h2 [2 * 2 * 32768];
// per-direction distributed monotonic arrival counters: [dir][8], 128B apart
__device__ __align__(128) unsigned g_cnt[2 * 32];

// ---------------- packed fp32 helpers ----------------
__device__ __forceinline__ void fma2(unsigned long long& d, unsigned long long a,
                                     unsigned long long b) {
    asm("fma.rn.f32x2 %0, %1, %2, %0;" : "+l"(d) : "l"(a), "l"(b));
}
__device__ __forceinline__ float2 up2(unsigned long long u) {
    float2 f; asm("mov.b64 {%0,%1}, %2;" : "=f"(f.x), "=f"(f.y) : "l"(u)); return f;
}
__device__ __forceinline__ float sigf(float x) { return 1.0f / (1.0f + expf(-x)); }
// fast activations (MUFU.TANH, sm_75+)
__device__ __forceinline__ float tanh_fast(float x) {
    float r; asm("tanh.approx.f32 %0, %1;" : "=f"(r) : "f"(x)); return r;
}
__device__ __forceinline__ float sig_fast(float x) {
    return fmaf(tanh_fast(0.5f * x), 0.5f, 0.5f);
}

// ---------------- embedding gather ----------------
__global__ void embed_kernel(const int* __restrict__ tokens,
                             const float* __restrict__ emb,
                             float* __restrict__ x0) {
    int i = blockIdx.x * 256 + threadIdx.x;
    if (i >= BT * 128) return;
    int row = i >> 7;
    int c4  = (i & 127) << 2;
    int tok = tokens[row];
    *(float4*)&x0[row * 512 + c4] = *(const float4*)&emb[tok * 512 + c4];
}

// ---------------- SGEMM: C = A(MxK) @ W(KxN) + bias (R13, unchanged) ----------------
__global__ void __launch_bounds__(256, 2)
sgemm_bias(const float* __restrict__ A, const float* __restrict__ W,
           const float* __restrict__ bias, float* __restrict__ C,
           int M, int N, int K) {
    __shared__ float As2[2][8][256];   // [buf][k][2*row+lane] (dup)
    __shared__ float Bs [2][8][128];   // [buf][k][col]

    int tid = threadIdx.x;
    int bm = blockIdx.y * 128;
    int bn = blockIdx.x * 128;
    int tx = tid & 15, ty = tid >> 4;

    int a_row = tid >> 1;
    int a_col = (tid & 1) * 4;
    int b_row = tid >> 5;
    int b_col = (tid & 31) * 4;

    unsigned long long acc[8][4];
    #pragma unroll
    for (int i = 0; i < 8; i++)
        #pragma unroll
        for (int j = 0; j < 4; j++) acc[i][j] = 0ull;

    const float* Ap = A + (size_t)(bm + a_row) * K + a_col;
    const float* Wp = W + (size_t)b_row * N + bn + b_col;

    {
        float4 av = *(const float4*)(Ap);
        float4 bv = *(const float4*)(Wp);
        *(float2*)&As2[0][a_col + 0][2 * a_row] = make_float2(av.x, av.x);
        *(float2*)&As2[0][a_col + 1][2 * a_row] = make_float2(av.y, av.y);
        *(float2*)&As2[0][a_col + 2][2 * a_row] = make_float2(av.z, av.z);
        *(float2*)&As2[0][a_col + 3][2 * a_row] = make_float2(av.w, av.w);
        *(float4*)&Bs[0][b_row][b_col] = bv;
    }
    __syncthreads();

    int cur = 0;
    for (int k0 = 8; k0 <= K; k0 += 8) {
        float4 av, bv;
        bool more = (k0 < K);
        if (more) {
            av = *(const float4*)(Ap + k0);
            bv = *(const float4*)(Wp + (size_t)k0 * N);
        }

        #pragma unroll
        for (int k = 0; k < 8; k++) {
            ulonglong2 A0 = *(const ulonglong2*)&As2[cur][k][2 * (ty * 4)];
            ulonglong2 A1 = *(const ulonglong2*)&As2[cur][k][2 * (ty * 4 + 2)];
            ulonglong2 A2 = *(const ulonglong2*)&As2[cur][k][2 * (64 + ty * 4)];
            ulonglong2 A3 = *(const ulonglong2*)&As2[cur][k][2 * (64 + ty * 4 + 2)];
            ulonglong2 B0 = *(const ulonglong2*)&Bs[cur][k][4 * tx];
            ulonglong2 B1 = *(const ulonglong2*)&Bs[cur][k][64 + 4 * tx];
            unsigned long long ap[8] = {A0.x, A0.y, A1.x, A1.y, A2.x, A2.y, A3.x, A3.y};
            unsigned long long bp[4] = {B0.x, B0.y, B1.x, B1.y};
            #pragma unroll
            for (int r = 0; r < 8; r++)
                #pragma unroll
                for (int c = 0; c < 4; c++)
                    fma2(acc[r][c], ap[r], bp[c]);
        }

        if (more) {
            int nxt = cur ^ 1;
            *(float2*)&As2[nxt][a_col + 0][2 * a_row] = make_float2(av.x, av.x);
            *(float2*)&As2[nxt][a_col + 1][2 * a_row] = make_float2(av.y, av.y);
            *(float2*)&As2[nxt][a_col + 2][2 * a_row] = make_float2(av.z, av.z);
            *(float2*)&As2[nxt][a_col + 3][2 * a_row] = make_float2(av.w, av.w);
            *(float4*)&Bs[nxt][b_row][b_col] = bv;
            __syncthreads();
            cur = nxt;
        }
    }

    float4 bs0 = *(const float4*)&bias[bn + 4 * tx];
    float4 bs1 = *(const float4*)&bias[bn + 64 + 4 * tx];

    #pragma unroll
    for (int i = 0; i < 8; i++) {
        int row = bm + ((i < 4) ? (ty * 4 + i) : (64 + ty * 4 + (i - 4)));
        float2 p0 = up2(acc[i][0]);
        float2 p1 = up2(acc[i][1]);
        float2 p2 = up2(acc[i][2]);
        float2 p3 = up2(acc[i][3]);
        float* Cr = C + (size_t)row * N;
        *(float4*)&Cr[bn + 4 * tx] =
            make_float4(p0.x + bs0.x, p0.y + bs0.y, p1.x + bs0.z, p1.y + bs0.w);
        *(float4*)&Cr[bn + 64 + 4 * tx] =
            make_float4(p2.x + bs1.x, p2.y + bs1.y, p3.x + bs1.z, p3.y + bs1.w);
    }
}

// ---------------- persistent bidirectional LSTM scan (4r x 4c split-k, split epilogue) ----------------
// 128 blocks x 256 threads. dir = blockIdx>>6, u0 = (blockIdx&63)*8.
// Thread: kh = tid>>7 (k parity), q = tid&127, tx = q&7 (unit), ty = q>>3.
// GEMM: rows 4ty..4ty+3 x unit u0+tx's 4 gates over kp of parity kh (R15).
// Epilogue SPLIT: half kh owns local rows 2kh, 2kh+1 (2 cells/thread); reduction is
//   symmetric (each half stores the 2 rows it does NOT own, reads its own).
// Activations: tanh.approx.f32; sigmoid via 0.5*tanh(x/2)+0.5 (5 MUFU/cell).
// Sync: per-direction split barrier (R14, unchanged).
__global__ void __launch_bounds__(256, 1)
lstm_scan(const float* __restrict__ xzf, const float* __restrict__ xzb,
          const float* __restrict__ Whf, const float* __restrict__ Whb,
          float* __restrict__ out, float* __restrict__ est_h, float* __restrict__ est_c) {
    extern __shared__ float sm[];
    float* w_s   = sm;                       // 17408 floats
    float* h_s   = sm + WS_F;                // 33792 floats (kp stride 132)
    float* red_s = sm + WS_F + HS_F;         // 2048 floats

    int tid = threadIdx.x;
    int dir = blockIdx.x >> 6;
    int blk = blockIdx.x & 63;
    int u0  = blk * 8;
    unsigned* my_cnt = &g_cnt[dir * 32 + (blk & 7)];
    const float* xz = dir ? xzb : xzf;
    const float* Wh = dir ? Whb : Whf;

    // stage Wh slice (once), bank-staggered layout
    for (int i = tid; i < 256 * 64; i += 256) {
        int kp = i >> 6, rem = i & 63;
        int ul = rem >> 3, w8 = rem & 7;
        int g = w8 >> 1, j = w8 & 1;
        w_s[kp * 68 + 8 * ul + 4 * (ul >> 2) + w8] =
            Wh[(size_t)(2 * kp + j) * GG + g * UU + u0 + ul];
    }
    __syncthreads();

    int kh = tid >> 7;
    int q  = tid & 127;
    int tx = q & 7;
    int ty = q >> 3;                       // 0..15
    const float* hp = h_s + 8 * ty;        // + kp*132
    const float* wq = w_s + 8 * tx + 4 * (tx >> 2);   // + kp*68

    int eu  = u0 + tx;
    int ekp = eu >> 1, elane = eu & 1;

    int rs = 2 * kh;                       // local rows owned by this half
    int ro = 2 - 2 * kh;                   // local rows given to the other half
    int rowA = 4 * ty + rs;                // global rows: rowA, rowA+1

    float cc[2] = {0.f, 0.f};

    for (int t = 0; t < TT; t++) {
        int ttv = dir ? (TT - 1 - t) : t;

        // prefetch input projections for this thread's 2 cells
        float za[2][4];
        #pragma unroll
        for (int j = 0; j < 2; j++)
            #pragma unroll
            for (int g = 0; g < 4; g++)
                za[j][g] = xz[(size_t)((rowA + j) * TT + ttv) * GG + g * UU + eu];

        float s[4][4];
        #pragma unroll
        for (int r = 0; r < 4; r++)
            #pragma unroll
            for (int c = 0; c < 4; c++) s[r][c] = 0.f;

        if (t > 0) {
            // wait: all 64 blocks of THIS direction arrived for step t-1
            if (tid < 8) {
                const unsigned* f = &g_cnt[dir * 32 + tid];
                unsigned target = 8u * (unsigned)t;
                unsigned v;
                do {
                    asm volatile("ld.acquire.gpu.u32 %0, [%1];" : "=r"(v) : "l"(f));
                } while (v < target);
            }
            __syncthreads();

            const float* hg = g_h2 + ((t & 1) * 2 + dir) * 32768;

            // stage chunk 0 (kp 0..63)
            #pragma unroll
            for (int j = 0; j < 8; j++) {
                int i = tid * 4 + j * 1024;
                float4 v = __ldcg((const float4*)(hg + i));
                *(float4*)&h_s[(i >> 7) * 132 + (i & 127)] = v;
            }
            __syncthreads();

            unsigned long long acc[4][4];
            #pragma unroll
            for (int r = 0; r < 4; r++)
                #pragma unroll
                for (int c = 0; c < 4; c++) acc[r][c] = 0ull;

            #pragma unroll
            for (int ch = 0; ch < 4; ch++) {
                float4 pre[8];
                if (ch < 3) {
                    #pragma unroll
                    for (int j = 0; j < 8; j++)
                        pre[j] = __ldcg((const float4*)(hg + 8192 * (ch + 1) + tid * 4 + j * 1024));
                }

                const float* hpc = hp + (size_t)(64 * ch + kh) * 132;
                const float* wqc = wq + (size_t)(64 * ch + kh) * 68;
                #pragma unroll 8
                for (int i2 = 0; i2 < 32; i2++) {
                    ulonglong2 ha = *(const ulonglong2*)(hpc + i2 * 264);
                    ulonglong2 hb = *(const ulonglong2*)(hpc + i2 * 264 + 4);
                    ulonglong2 wa = *(const ulonglong2*)(wqc + i2 * 136);
                    ulonglong2 wb = *(const ulonglong2*)(wqc + i2 * 136 + 4);
                    fma2(acc[0][0], ha.x, wa.x); fma2(acc[0][1], ha.x, wa.y);
                    fma2(acc[0][2], ha.x, wb.x); fma2(acc[0][3], ha.x, wb.y);
                    fma2(acc[1][0], ha.y, wa.x); fma2(acc[1][1], ha.y, wa.y);
                    fma2(acc[1][2], ha.y, wb.x); fma2(acc[1][3], ha.y, wb.y);
                    fma2(acc[2][0], hb.x, wa.x); fma2(acc[2][1], hb.x, wa.y);
                    fma2(acc[2][2], hb.x, wb.x); fma2(acc[2][3], hb.x, wb.y);
                    fma2(acc[3][0], hb.y, wa.x); fma2(acc[3][1], hb.y, wa.y);
                    fma2(acc[3][2], hb.y, wb.x); fma2(acc[3][3], hb.y, wb.y);
                }

                if (ch < 3) {
                    #pragma unroll
                    for (int j = 0; j < 8; j++) {
                        int i = 8192 * (ch + 1) + tid * 4 + j * 1024;
                        *(float4*)&h_s[(i >> 7) * 132 + (i & 127)] = pre[j];
                    }
                    __syncthreads();
                }
            }

            // collapse f32x2 lanes
            #pragma unroll
            for (int r = 0; r < 4; r++)
                #pragma unroll
                for (int c = 0; c < 4; c++) {
                    float2 p = up2(acc[r][c]);
                    s[r][c] = p.x + p.y;
                }

            // symmetric cross-half reduction: store the 2 rows the OTHER half owns
            #pragma unroll
            for (int j = 0; j < 2; j++)
                *(float4*)&red_s[(ro + j) * 512 + q * 4] =
                    make_float4(s[ro + j][0], s[ro + j][1], s[ro + j][2], s[ro + j][3]);
            __syncthreads();
            #pragma unroll
            for (int j = 0; j < 2; j++) {
                float4 v = *(const float4*)&red_s[(rs + j) * 512 + q * 4];
                s[rs + j][0] += v.x; s[rs + j][1] += v.y;
                s[rs + j][2] += v.z; s[rs + j][3] += v.w;
            }
        }

        // epilogue: each thread handles its 2 owned cells (fast activations)
        float h2v[2];
        #pragma unroll
        for (int j = 0; j < 2; j++) {
            float gi = sig_fast(za[j][0] + s[rs + j][0]);
            float gf = sig_fast(za[j][1] + s[rs + j][1]);
            float gg = tanh_fast(za[j][2] + s[rs + j][2]);
            float go = sig_fast(za[j][3] + s[rs + j][3]);
            cc[j] = gf * cc[j] + gi * gg;
            h2v[j] = go * tanh_fast(cc[j]);
        }

        bool not_last = (t + 1 < TT);
        if (not_last) {
            float* hn = g_h2 + (((t + 1) & 1) * 2 + dir) * 32768;
            #pragma unroll
            for (int j = 0; j < 2; j++)
                hn[ekp * 128 + 2 * (rowA + j) + elane] = h2v[j];
            __syncthreads();                 // all h stores of this block done
            if (tid == 0)
                asm volatile("red.release.gpu.global.add.u32 [%0], %1;"
                             :: "l"(my_cnt), "r"(1u) : "memory");
        }

        // overlap other blocks' arrivals (wait happens next iteration)
        #pragma unroll
        for (int j = 0; j < 2; j++)
            out[(size_t)((rowA + j) * TT + ttv) * 1024 + dir * UU + eu] = h2v[j];

        if (est_h != nullptr && t == TT - 1) {
            #pragma unroll
            for (int j = 0; j < 2; j++) {
                est_h[(rowA + j) * 1024 + dir * UU + eu] = h2v[j];
                est_c[(rowA + j) * 1024 + dir * UU + eu] = cc[j];
            }
        }
    }
}

// ---------------- launch ----------------
extern "C" void kernel_launch(void* const* d_in, const int* in_sizes, int n_in,
                              void* d_out, int out_size) {
    const int*   tokens = (const int*)  d_in[0];
    const float* emb    = (const float*)d_in[1];
    const float* Wx_f0 = (const float*)d_in[2];
    const float* Wh_f0 = (const float*)d_in[3];
    const float* b_f0  = (const float*)d_in[4];
    const float* Wx_b0 = (const float*)d_in[5];
    const float* Wh_b0 = (const float*)d_in[6];
    const float* b_b0  = (const float*)d_in[7];
    const float* Wx_f1 = (const float*)d_in[8];
    const float* Wh_f1 = (const float*)d_in[9];
    const float* b_f1  = (const float*)d_in[10];
    const float* Wx_b1 = (const float*)d_in[11];
    const float* Wh_b1 = (const float*)d_in[12];
    const float* b_b1  = (const float*)d_in[13];
    float* out = (float*)d_out;

    float *x0p, *y0p, *xzfp, *xzbp;
    void* cntp;
    cudaGetSymbolAddress((void**)&x0p,  g_x0);
    cudaGetSymbolAddress((void**)&y0p,  g_y0);
    cudaGetSymbolAddress((void**)&xzfp, g_xzf);
    cudaGetSymbolAddress((void**)&xzbp, g_xzb);
    cudaGetSymbolAddress(&cntp, g_cnt);

    cudaFuncSetAttribute(lstm_scan, cudaFuncAttributeMaxDynamicSharedMemorySize, SCAN_SMEM);

    embed_kernel<<<(BT * 128 + 255) / 256, 256>>>(tokens, emb, x0p);

    dim3 g0(GG / 128, BT / 128);
    sgemm_bias<<<g0, 256>>>(x0p, Wx_f0, b_f0, xzfp, BT, GG, 512);
    sgemm_bias<<<g0, 256>>>(x0p, Wx_b0, b_b0, xzbp, BT, GG, 512);

    cudaMemsetAsync(cntp, 0, 2 * 32 * sizeof(unsigned));
    lstm_scan<<<NBLK, 256, SCAN_SMEM>>>(xzfp, xzbp, Wh_f0, Wh_b0, y0p,
                                        (float*)nullptr, (float*)nullptr);

    sgemm_bias<<<g0, 256>>>(y0p, Wx_f1, b_f1, xzfp, BT, GG, 1024);
    sgemm_bias<<<g0, 256>>>(y0p, Wx_b1, b_b1, xzbp, BT, GG, 1024);

    float* est_h = out + (size_t)BT * 1024;
    float* est_c = est_h + BB * 1024;
    cudaMemsetAsync(cntp, 0, 2 * 32 * sizeof(unsigned));
    lstm_scan<<<NBLK, 256, SCAN_SMEM>>>(xzfp, xzbp, Wh_f1, Wh_b1, out, est_h, est_c);
}

// round 17
// speedup vs baseline: 3.5924x; 1.3108x over previous
#include <cuda_runtime.h>
#include <cuda_bf16.h>
#include <cstdint>

#define BB 64
#define TT 256
#define UU 512
#define GG 2048
#define BT (BB*TT)

#define NBLK 128
#define WS_F   17408
#define HS_F   33792
#define RS_F   2048
#define SCAN_SMEM ((WS_F + HS_F + RS_F) * 4)   // 212992 B

// ---------------- static scratch ----------------
__device__ __align__(128) float g_x0 [BT * 512];
__device__ __align__(128) float g_y0 [BT * 1024];
__device__ __align__(128) float g_xzf[BT * GG];
__device__ __align__(128) float g_xzb[BT * GG];
__device__ __align__(128) float g_h2 [2 * 2 * 32768];
__device__ __align__(128) unsigned g_cnt[2 * 32];

// ---------------- helpers ----------------
__device__ __forceinline__ void fma2(unsigned long long& d, unsigned long long a,
                                     unsigned long long b) {
    asm("fma.rn.f32x2 %0, %1, %2, %0;" : "+l"(d) : "l"(a), "l"(b));
}
__device__ __forceinline__ float2 up2(unsigned long long u) {
    float2 f; asm("mov.b64 {%0,%1}, %2;" : "=f"(f.x), "=f"(f.y) : "l"(u)); return f;
}
__device__ __forceinline__ float tanh_fast(float x) {
    float r; asm("tanh.approx.f32 %0, %1;" : "=f"(r) : "f"(x)); return r;
}
__device__ __forceinline__ float sig_fast(float x) {
    return fmaf(tanh_fast(0.5f * x), 0.5f, 0.5f);
}

// tensor-core primitives
__device__ __forceinline__ void ldsm_x4(unsigned* r, unsigned addr) {
    asm volatile("ldmatrix.sync.aligned.m8n8.x4.shared.b16 {%0,%1,%2,%3}, [%4];"
                 : "=r"(r[0]), "=r"(r[1]), "=r"(r[2]), "=r"(r[3]) : "r"(addr));
}
__device__ __forceinline__ void ldsm_x2t(unsigned* r, unsigned addr) {
    asm volatile("ldmatrix.sync.aligned.m8n8.x2.trans.shared.b16 {%0,%1}, [%2];"
                 : "=r"(r[0]), "=r"(r[1]) : "r"(addr));
}
__device__ __forceinline__ void mma_bf16(float* d, const unsigned* a, const unsigned* b) {
    asm volatile("mma.sync.aligned.m16n8k16.row.col.f32.bf16.bf16.f32 "
                 "{%0,%1,%2,%3}, {%4,%5,%6,%7}, {%8,%9}, {%0,%1,%2,%3};"
                 : "+f"(d[0]), "+f"(d[1]), "+f"(d[2]), "+f"(d[3])
                 : "r"(a[0]), "r"(a[1]), "r"(a[2]), "r"(a[3]), "r"(b[0]), "r"(b[1]));
}

union Pk8 { __nv_bfloat16 h[8]; uint4 u; };
__device__ __forceinline__ void split8(const float* x, Pk8& hi, Pk8& lo) {
    #pragma unroll
    for (int j = 0; j < 8; j++) {
        __nv_bfloat16 h = __float2bfloat16(x[j]);
        hi.h[j] = h;
        lo.h[j] = __float2bfloat16(x[j] - __bfloat162float(h));
    }
}

// ---------------- embedding gather ----------------
__global__ void embed_kernel(const int* __restrict__ tokens,
                             const float* __restrict__ emb,
                             float* __restrict__ x0) {
    int i = blockIdx.x * 256 + threadIdx.x;
    if (i >= BT * 128) return;
    int row = i >> 7;
    int c4  = (i & 127) << 2;
    int tok = tokens[row];
    *(float4*)&x0[row * 512 + c4] = *(const float4*)&emb[tok * 512 + c4];
}

// ---------------- tensor SGEMM: C = A(MxK)@W(KxN)+bias, bf16 3-term split ----------------
// Block 128x128, 256 thr = 8 warps (warp grid 4m x 2n, warp tile 32m x 64n), k-slab 16.
// smem (bf16 units per buffer): AH [128][24] @0, AL @3072, BH [16][136] @6144, BL @8320.
#define TGB 10496    // bf16 units per buffer
__global__ void __launch_bounds__(256)
tgemm_bias(const float* __restrict__ A, const float* __restrict__ W,
           const float* __restrict__ bias, float* __restrict__ C,
           int M, int N, int K) {
    __shared__ __nv_bfloat16 smb[2 * TGB];

    int tid = threadIdx.x;
    int bn = blockIdx.x * 128;
    int bm = blockIdx.y * 128;

    int arow = tid >> 1, acol = (tid & 1) * 8;
    int brow = tid >> 4, bcol = (tid & 15) * 8;

    const float* Ap = A + (size_t)(bm + arow) * K + acol;
    const float* Wp = W + (size_t)brow * N + bn + bcol;

    int w = tid >> 5, lam = tid & 31;
    int wm = (w & 3) * 32, wn = (w >> 2) * 64;
    int r16 = lam & 15, cb8 = (lam >> 4) * 8;

    unsigned sbase = (unsigned)__cvta_generic_to_shared(smb);
    unsigned aH0 = sbase + (unsigned)(((wm + r16) * 24 + cb8) << 1);
    unsigned aH1 = aH0 + (16 * 24 << 1);
    unsigned aLo = (3072 << 1);
    unsigned bB  = sbase + (unsigned)((6144 + r16 * 136 + wn) << 1);
    unsigned bLo = (2176 << 1);

    float acc[2][8][4];
    #pragma unroll
    for (int m = 0; m < 2; m++)
        #pragma unroll
        for (int n = 0; n < 8; n++)
            #pragma unroll
            for (int j = 0; j < 4; j++) acc[m][n][j] = 0.f;

    // prologue: stage k-slab 0 into buf 0
    {
        float av[8], bv[8];
        *(float4*)&av[0] = *(const float4*)(Ap);
        *(float4*)&av[4] = *(const float4*)(Ap + 4);
        *(float4*)&bv[0] = *(const float4*)(Wp);
        *(float4*)&bv[4] = *(const float4*)(Wp + 4);
        Pk8 hi, lo;
        split8(av, hi, lo);
        *(uint4*)&smb[arow * 24 + acol]        = hi.u;
        *(uint4*)&smb[3072 + arow * 24 + acol] = lo.u;
        split8(bv, hi, lo);
        *(uint4*)&smb[6144 + brow * 136 + bcol] = hi.u;
        *(uint4*)&smb[8320 + brow * 136 + bcol] = lo.u;
    }
    __syncthreads();

    int cur = 0;
    for (int k0 = 16; k0 <= K; k0 += 16) {
        bool more = (k0 < K);
        float av[8], bv[8];
        if (more) {
            *(float4*)&av[0] = *(const float4*)(Ap + k0);
            *(float4*)&av[4] = *(const float4*)(Ap + k0 + 4);
            *(float4*)&bv[0] = *(const float4*)(Wp + (size_t)k0 * N);
            *(float4*)&bv[4] = *(const float4*)(Wp + (size_t)k0 * N + 4);
        }

        unsigned bo = (unsigned)(cur * (TGB << 1));
        unsigned fAH0[4], fAH1[4], fAL0[4], fAL1[4];
        ldsm_x4(fAH0, aH0 + bo);
        ldsm_x4(fAH1, aH1 + bo);
        ldsm_x4(fAL0, aH0 + bo + aLo);
        ldsm_x4(fAL1, aH1 + bo + aLo);
        #pragma unroll
        for (int nt = 0; nt < 8; nt++) {
            unsigned bh[2], bl[2];
            ldsm_x2t(bh, bB + bo + (nt * 8 << 1));
            ldsm_x2t(bl, bB + bo + bLo + (nt * 8 << 1));
            mma_bf16(acc[0][nt], fAH0, bh);
            mma_bf16(acc[0][nt], fAH0, bl);
            mma_bf16(acc[0][nt], fAL0, bh);
            mma_bf16(acc[1][nt], fAH1, bh);
            mma_bf16(acc[1][nt], fAH1, bl);
            mma_bf16(acc[1][nt], fAL1, bh);
        }

        if (more) {
            int nxt = cur ^ 1;
            __nv_bfloat16* sb = smb + nxt * TGB;
            Pk8 hi, lo;
            split8(av, hi, lo);
            *(uint4*)&sb[arow * 24 + acol]        = hi.u;
            *(uint4*)&sb[3072 + arow * 24 + acol] = lo.u;
            split8(bv, hi, lo);
            *(uint4*)&sb[6144 + brow * 136 + bcol] = hi.u;
            *(uint4*)&sb[8320 + brow * 136 + bcol] = lo.u;
            __syncthreads();
            cur = nxt;
        }
    }

    // epilogue
    int g = lam >> 2, tg2 = (lam & 3) * 2;
    #pragma unroll
    for (int mt = 0; mt < 2; mt++) {
        int row = bm + wm + mt * 16 + g;
        #pragma unroll
        for (int nt = 0; nt < 8; nt++) {
            int col = bn + wn + nt * 8 + tg2;
            float b0 = bias[col], b1 = bias[col + 1];
            *(float2*)&C[(size_t)row * N + col] =
                make_float2(acc[mt][nt][0] + b0, acc[mt][nt][1] + b1);
            *(float2*)&C[(size_t)(row + 8) * N + col] =
                make_float2(acc[mt][nt][2] + b0, acc[mt][nt][3] + b1);
        }
    }
}

// ---------------- persistent bidirectional LSTM scan (R16, unchanged) ----------------
__global__ void __launch_bounds__(256, 1)
lstm_scan(const float* __restrict__ xzf, const float* __restrict__ xzb,
          const float* __restrict__ Whf, const float* __restrict__ Whb,
          float* __restrict__ out, float* __restrict__ est_h, float* __restrict__ est_c) {
    extern __shared__ float sm[];
    float* w_s   = sm;
    float* h_s   = sm + WS_F;
    float* red_s = sm + WS_F + HS_F;

    int tid = threadIdx.x;
    int dir = blockIdx.x >> 6;
    int blk = blockIdx.x & 63;
    int u0  = blk * 8;
    unsigned* my_cnt = &g_cnt[dir * 32 + (blk & 7)];
    const float* xz = dir ? xzb : xzf;
    const float* Wh = dir ? Whb : Whf;

    for (int i = tid; i < 256 * 64; i += 256) {
        int kp = i >> 6, rem = i & 63;
        int ul = rem >> 3, w8 = rem & 7;
        int g = w8 >> 1, j = w8 & 1;
        w_s[kp * 68 + 8 * ul + 4 * (ul >> 2) + w8] =
            Wh[(size_t)(2 * kp + j) * GG + g * UU + u0 + ul];
    }
    __syncthreads();

    int kh = tid >> 7;
    int q  = tid & 127;
    int tx = q & 7;
    int ty = q >> 3;
    const float* hp = h_s + 8 * ty;
    const float* wq = w_s + 8 * tx + 4 * (tx >> 2);

    int eu  = u0 + tx;
    int ekp = eu >> 1, elane = eu & 1;

    int rs = 2 * kh;
    int ro = 2 - 2 * kh;
    int rowA = 4 * ty + rs;

    float cc[2] = {0.f, 0.f};

    for (int t = 0; t < TT; t++) {
        int ttv = dir ? (TT - 1 - t) : t;

        float za[2][4];
        #pragma unroll
        for (int j = 0; j < 2; j++)
            #pragma unroll
            for (int g = 0; g < 4; g++)
                za[j][g] = xz[(size_t)((rowA + j) * TT + ttv) * GG + g * UU + eu];

        float s[4][4];
        #pragma unroll
        for (int r = 0; r < 4; r++)
            #pragma unroll
            for (int c = 0; c < 4; c++) s[r][c] = 0.f;

        if (t > 0) {
            if (tid < 8) {
                const unsigned* f = &g_cnt[dir * 32 + tid];
                unsigned target = 8u * (unsigned)t;
                unsigned v;
                do {
                    asm volatile("ld.acquire.gpu.u32 %0, [%1];" : "=r"(v) : "l"(f));
                } while (v < target);
            }
            __syncthreads();

            const float* hg = g_h2 + ((t & 1) * 2 + dir) * 32768;

            #pragma unroll
            for (int j = 0; j < 8; j++) {
                int i = tid * 4 + j * 1024;
                float4 v = __ldcg((const float4*)(hg + i));
                *(float4*)&h_s[(i >> 7) * 132 + (i & 127)] = v;
            }
            __syncthreads();

            unsigned long long acc[4][4];
            #pragma unroll
            for (int r = 0; r < 4; r++)
                #pragma unroll
                for (int c = 0; c < 4; c++) acc[r][c] = 0ull;

            #pragma unroll
            for (int ch = 0; ch < 4; ch++) {
                float4 pre[8];
                if (ch < 3) {
                    #pragma unroll
                    for (int j = 0; j < 8; j++)
                        pre[j] = __ldcg((const float4*)(hg + 8192 * (ch + 1) + tid * 4 + j * 1024));
                }

                const float* hpc = hp + (size_t)(64 * ch + kh) * 132;
                const float* wqc = wq + (size_t)(64 * ch + kh) * 68;
                #pragma unroll 8
                for (int i2 = 0; i2 < 32; i2++) {
                    ulonglong2 ha = *(const ulonglong2*)(hpc + i2 * 264);
                    ulonglong2 hb = *(const ulonglong2*)(hpc + i2 * 264 + 4);
                    ulonglong2 wa = *(const ulonglong2*)(wqc + i2 * 136);
                    ulonglong2 wb = *(const ulonglong2*)(wqc + i2 * 136 + 4);
                    fma2(acc[0][0], ha.x, wa.x); fma2(acc[0][1], ha.x, wa.y);
                    fma2(acc[0][2], ha.x, wb.x); fma2(acc[0][3], ha.x, wb.y);
                    fma2(acc[1][0], ha.y, wa.x); fma2(acc[1][1], ha.y, wa.y);
                    fma2(acc[1][2], ha.y, wb.x); fma2(acc[1][3], ha.y, wb.y);
                    fma2(acc[2][0], hb.x, wa.x); fma2(acc[2][1], hb.x, wa.y);
                    fma2(acc[2][2], hb.x, wb.x); fma2(acc[2][3], hb.x, wb.y);
                    fma2(acc[3][0], hb.y, wa.x); fma2(acc[3][1], hb.y, wa.y);
                    fma2(acc[3][2], hb.y, wb.x); fma2(acc[3][3], hb.y, wb.y);
                }

                if (ch < 3) {
                    #pragma unroll
                    for (int j = 0; j < 8; j++) {
                        int i = 8192 * (ch + 1) + tid * 4 + j * 1024;
                        *(float4*)&h_s[(i >> 7) * 132 + (i & 127)] = pre[j];
                    }
                    __syncthreads();
                }
            }

            #pragma unroll
            for (int r = 0; r < 4; r++)
                #pragma unroll
                for (int c = 0; c < 4; c++) {
                    float2 p = up2(acc[r][c]);
                    s[r][c] = p.x + p.y;
                }

            #pragma unroll
            for (int j = 0; j < 2; j++)
                *(float4*)&red_s[(ro + j) * 512 + q * 4] =
                    make_float4(s[ro + j][0], s[ro + j][1], s[ro + j][2], s[ro + j][3]);
            __syncthreads();
            #pragma unroll
            for (int j = 0; j < 2; j++) {
                float4 v = *(const float4*)&red_s[(rs + j) * 512 + q * 4];
                s[rs + j][0] += v.x; s[rs + j][1] += v.y;
                s[rs + j][2] += v.z; s[rs + j][3] += v.w;
            }
        }

        float h2v[2];
        #pragma unroll
        for (int j = 0; j < 2; j++) {
            float gi = sig_fast(za[j][0] + s[rs + j][0]);
            float gf = sig_fast(za[j][1] + s[rs + j][1]);
            float gg = tanh_fast(za[j][2] + s[rs + j][2]);
            float go = sig_fast(za[j][3] + s[rs + j][3]);
            cc[j] = gf * cc[j] + gi * gg;
            h2v[j] = go * tanh_fast(cc[j]);
        }

        bool not_last = (t + 1 < TT);
        if (not_last) {
            float* hn = g_h2 + (((t + 1) & 1) * 2 + dir) * 32768;
            #pragma unroll
            for (int j = 0; j < 2; j++)
                hn[ekp * 128 + 2 * (rowA + j) + elane] = h2v[j];
            __syncthreads();
            if (tid == 0)
                asm volatile("red.release.gpu.global.add.u32 [%0], %1;"
                             :: "l"(my_cnt), "r"(1u) : "memory");
        }

        #pragma unroll
        for (int j = 0; j < 2; j++)
            out[(size_t)((rowA + j) * TT + ttv) * 1024 + dir * UU + eu] = h2v[j];

        if (est_h != nullptr && t == TT - 1) {
            #pragma unroll
            for (int j = 0; j < 2; j++) {
                est_h[(rowA + j) * 1024 + dir * UU + eu] = h2v[j];
                est_c[(rowA + j) * 1024 + dir * UU + eu] = cc[j];
            }
        }
    }
}

// ---------------- launch ----------------
extern "C" void kernel_launch(void* const* d_in, const int* in_sizes, int n_in,
                              void* d_out, int out_size) {
    const int*   tokens = (const int*)  d_in[0];
    const float* emb    = (const float*)d_in[1];
    const float* Wx_f0 = (const float*)d_in[2];
    const float* Wh_f0 = (const float*)d_in[3];
    const float* b_f0  = (const float*)d_in[4];
    const float* Wx_b0 = (const float*)d_in[5];
    const float* Wh_b0 = (const float*)d_in[6];
    const float* b_b0  = (const float*)d_in[7];
    const float* Wx_f1 = (const float*)d_in[8];
    const float* Wh_f1 = (const float*)d_in[9];
    const float* b_f1  = (const float*)d_in[10];
    const float* Wx_b1 = (const float*)d_in[11];
    const float* Wh_b1 = (const float*)d_in[12];
    const float* b_b1  = (const float*)d_in[13];
    float* out = (float*)d_out;

    float *x0p, *y0p, *xzfp, *xzbp;
    void* cntp;
    cudaGetSymbolAddress((void**)&x0p,  g_x0);
    cudaGetSymbolAddress((void**)&y0p,  g_y0);
    cudaGetSymbolAddress((void**)&xzfp, g_xzf);
    cudaGetSymbolAddress((void**)&xzbp, g_xzb);
    cudaGetSymbolAddress(&cntp, g_cnt);

    cudaFuncSetAttribute(lstm_scan, cudaFuncAttributeMaxDynamicSharedMemorySize, SCAN_SMEM);

    embed_kernel<<<(BT * 128 + 255) / 256, 256>>>(tokens, emb, x0p);

    dim3 g0(GG / 128, BT / 128);
    tgemm_bias<<<g0, 256>>>(x0p, Wx_f0, b_f0, xzfp, BT, GG, 512);
    tgemm_bias<<<g0, 256>>>(x0p, Wx_b0, b_b0, xzbp, BT, GG, 512);

    cudaMemsetAsync(cntp, 0, 2 * 32 * sizeof(unsigned));
    lstm_scan<<<NBLK, 256, SCAN_SMEM>>>(xzfp, xzbp, Wh_f0, Wh_b0, y0p,
                                        (float*)nullptr, (float*)nullptr);

    tgemm_bias<<<g0, 256>>>(y0p, Wx_f1, b_f1, xzfp, BT, GG, 1024);
    tgemm_bias<<<g0, 256>>>(y0p, Wx_b1, b_b1, xzbp, BT, GG, 1024);

    float* est_h = out + (size_t)BT * 1024;
    float* est_c = est_h + BB * 1024;
    cudaMemsetAsync(cntp, 0, 2 * 32 * sizeof(unsigned));
    lstm_scan<<<NBLK, 256, SCAN_SMEM>>>(xzfp, xzbp, Wh_f1, Wh_b1, out, est_h, est_c);
}